// round 5
// baseline (speedup 1.0000x reference)
#include <cuda_runtime.h>
#include <math.h>

#define NN 50000
#define EE 250000
#define HD 64
#define NH 4
#define FDR 768         // 3 relations * 4 heads * 64
#define IND 256
#define SCALEF 0.125f   // 1/sqrt(64)
#define EPS_BN 1e-5f
#define LDW 136                          // smem row stride (words), hi/lo interleaved
#define A_SM_FLOATS (128 * LDW)
#define B_SM_FLOATS (64 * LDW)
#define GEMM_SMEM ((A_SM_FLOATS + B_SM_FLOATS) * 4)   // 104448 B

// ---------------- scratch (static device globals; no allocation) -------------
__device__ float g_fs[(size_t)NN * FDR];
__device__ float g_fd[(size_t)NN * FDR];
__device__ float g_p[3u * EE * NH];
__device__ float g_den[3 * NN * NH];
__device__ float g_hmean[NN * HD];
__device__ float g_h[NN * HD];
__device__ float g_bnstat[2 * HD];

// ---------------- fills -------------------------------------------------------
__global__ void fill_kernel(float* __restrict__ p, int n, float v) {
    int i = blockIdx.x * blockDim.x + threadIdx.x;
    int stride = gridDim.x * blockDim.x;
    for (; i < n; i += stride) p[i] = v;
}

// ---------------- tf32 helpers ------------------------------------------------
__device__ __forceinline__ unsigned f2tf32(float x) {
    unsigned r;
    asm("cvt.rna.tf32.f32 %0, %1;" : "=r"(r) : "f"(x));
    return r;
}
__device__ __forceinline__ void split2(float x, float& hi, float& lo) {
    unsigned h = f2tf32(x);
    hi = __uint_as_float(h);
    lo = __uint_as_float(f2tf32(x - __uint_as_float(h)));
}
__device__ __forceinline__ void mma_tf32(float* c,
                                         float a0, float a1, float a2, float a3,
                                         float b0, float b1) {
    asm volatile("mma.sync.aligned.m16n8k8.row.col.f32.tf32.tf32.f32 "
                 "{%0,%1,%2,%3}, {%4,%5,%6,%7}, {%8,%9}, {%0,%1,%2,%3};"
                 : "+f"(c[0]), "+f"(c[1]), "+f"(c[2]), "+f"(c[3])
                 : "r"(__float_as_uint(a0)), "r"(__float_as_uint(a1)),
                   "r"(__float_as_uint(a2)), "r"(__float_as_uint(a3)),
                   "r"(__float_as_uint(b0)), "r"(__float_as_uint(b1)));
}

// ---------------- GEMM: C[M,NcC] = A[M,64] @ B-blocks (+bias)(+relu) ---------
// Block tile 128x64, 8 warps (4 row-groups x 2 col-groups), warp tile 32x32.
// 3xTF32 split; operands pre-split hi/lo-interleaved in smem (stride 136 words,
// conflict-free for both fragment patterns). Inner loop: LDS.64 + HMMA only.
template <int BIAS, int RELU>
__global__ void gemm_tf32s(const float* __restrict__ A,
                           const float* __restrict__ B,
                           const float* __restrict__ bias,
                           float* __restrict__ C, int M, int NcC, int ldb) {
    extern __shared__ float sm[];
    float* As = sm;                    // [128][LDW] (hi,lo pairs)
    float* Bs = sm + A_SM_FLOATS;      // [64][LDW]

    const int bm = blockIdx.y * 128;
    const int bn = blockIdx.x * 64;
    const int tid = threadIdx.x;
    const float* Bblk = B + (size_t)(bn >> 8) * (64 * 256) + (bn & 255);

    // load + pre-split A (128x64) and B (64x64), hi/lo interleaved
    for (int i = tid; i < 128 * 16; i += 256) {
        int rr = i >> 4, c4 = (i & 15) << 2;
        int gr = bm + rr;
        float4 va = make_float4(0.f, 0.f, 0.f, 0.f);
        if (gr < M) va = *reinterpret_cast<const float4*>(&A[(size_t)gr * 64 + c4]);
        float hx, lx, hy, ly, hz, lz, hw, lw;
        split2(va.x, hx, lx); split2(va.y, hy, ly);
        split2(va.z, hz, lz); split2(va.w, hw, lw);
        *reinterpret_cast<float4*>(&As[rr * LDW + (c4 << 1)])     = make_float4(hx, lx, hy, ly);
        *reinterpret_cast<float4*>(&As[rr * LDW + (c4 << 1) + 4]) = make_float4(hz, lz, hw, lw);
    }
    for (int i = tid; i < 64 * 16; i += 256) {
        int rr = i >> 4, c4 = (i & 15) << 2;
        float4 vb = *reinterpret_cast<const float4*>(&Bblk[(size_t)rr * ldb + c4]);
        float hx, lx, hy, ly, hz, lz, hw, lw;
        split2(vb.x, hx, lx); split2(vb.y, hy, ly);
        split2(vb.z, hz, lz); split2(vb.w, hw, lw);
        *reinterpret_cast<float4*>(&Bs[rr * LDW + (c4 << 1)])     = make_float4(hx, lx, hy, ly);
        *reinterpret_cast<float4*>(&Bs[rr * LDW + (c4 << 1) + 4]) = make_float4(hz, lz, hw, lw);
    }
    __syncthreads();

    const int warp = tid >> 5, lane = tid & 31;
    const int rowg = warp >> 1, colg = warp & 1;
    const int rbase = rowg * 32, cbase = colg * 32;
    const int gid = lane >> 2, tig = lane & 3;

    float acc[2][4][4];
#pragma unroll
    for (int mb = 0; mb < 2; mb++)
#pragma unroll
        for (int nt = 0; nt < 4; nt++)
#pragma unroll
            for (int j = 0; j < 4; j++) acc[mb][nt][j] = 0.0f;

#pragma unroll
    for (int k0 = 0; k0 < 64; k0 += 8) {
        // A fragments: a[mb][pos] = (hi, lo) at rows {gid, gid+8} x cols {tig, tig+4}
        float2 a[2][4];
#pragma unroll
        for (int mb = 0; mb < 2; mb++) {
            int r0 = (rbase + mb * 16 + gid) * LDW;
            int r1 = r0 + 8 * LDW;
            a[mb][0] = *reinterpret_cast<const float2*>(&As[r0 + 2 * (k0 + tig)]);
            a[mb][1] = *reinterpret_cast<const float2*>(&As[r1 + 2 * (k0 + tig)]);
            a[mb][2] = *reinterpret_cast<const float2*>(&As[r0 + 2 * (k0 + tig + 4)]);
            a[mb][3] = *reinterpret_cast<const float2*>(&As[r1 + 2 * (k0 + tig + 4)]);
        }
#pragma unroll
        for (int nt = 0; nt < 4; nt++) {
            int n2 = 2 * (cbase + nt * 8 + gid);
            float2 b0 = *reinterpret_cast<const float2*>(&Bs[(k0 + tig) * LDW + n2]);
            float2 b1 = *reinterpret_cast<const float2*>(&Bs[(k0 + tig + 4) * LDW + n2]);
#pragma unroll
            for (int mb = 0; mb < 2; mb++) {
                mma_tf32(acc[mb][nt], a[mb][0].x, a[mb][1].x, a[mb][2].x, a[mb][3].x, b0.x, b1.x);
                mma_tf32(acc[mb][nt], a[mb][0].x, a[mb][1].x, a[mb][2].x, a[mb][3].x, b0.y, b1.y);
                mma_tf32(acc[mb][nt], a[mb][0].y, a[mb][1].y, a[mb][2].y, a[mb][3].y, b0.x, b1.x);
            }
        }
    }

#pragma unroll
    for (int mb = 0; mb < 2; mb++)
#pragma unroll
        for (int nt = 0; nt < 4; nt++) {
            int c = bn + cbase + nt * 8 + 2 * tig;
            float bb0 = 0.f, bb1 = 0.f;
            if (BIAS) { bb0 = bias[c]; bb1 = bias[c + 1]; }
#pragma unroll
            for (int half = 0; half < 2; half++) {
                int gr = bm + rbase + mb * 16 + gid + half * 8;
                if (gr >= M) continue;
                float v0 = acc[mb][nt][half * 2 + 0] + bb0;
                float v1 = acc[mb][nt][half * 2 + 1] + bb1;
                if (RELU) { v0 = fmaxf(v0, 0.0f); v1 = fmaxf(v1, 0.0f); }
                *reinterpret_cast<float2*>(&C[(size_t)gr * NcC + c]) = make_float2(v0, v1);
            }
        }
}

// ---------------- edge pass 1: dot + exp + denominator (all 3 relations) -----
__global__ void edge_softmax_all(const float* __restrict__ fs,
                                 const float* __restrict__ fd,
                                 const int* __restrict__ src0, const int* __restrict__ dst0,
                                 const int* __restrict__ src1, const int* __restrict__ dst1,
                                 const int* __restrict__ src2, const int* __restrict__ dst2,
                                 float* __restrict__ p_out, float* __restrict__ den) {
    int gw = blockIdx.x * 8 + (threadIdx.x >> 5);
    if (gw >= 3 * EE) return;
    int r = gw / EE, e = gw - r * EE;
    const int* sp = (r == 0) ? src0 : (r == 1) ? src1 : src2;
    const int* dp = (r == 0) ? dst0 : (r == 1) ? dst1 : dst2;
    int s = sp[e], d = dp[e];
    int lane = threadIdx.x & 31;
    int h = lane >> 3, sub = lane & 7;
    const float4* ps = reinterpret_cast<const float4*>(fs + (size_t)s * FDR + r * 256 + h * 64) + sub * 2;
    const float4* pd = reinterpret_cast<const float4*>(fd + (size_t)d * FDR + r * 256 + h * 64) + sub * 2;
    float4 a0 = ps[0], a1 = ps[1];
    float4 b0 = pd[0], b1 = pd[1];
    float v = a0.x * b0.x + a0.y * b0.y + a0.z * b0.z + a0.w * b0.w +
              a1.x * b1.x + a1.y * b1.y + a1.z * b1.z + a1.w * b1.w;
    v += __shfl_xor_sync(0xffffffffu, v, 4);
    v += __shfl_xor_sync(0xffffffffu, v, 2);
    v += __shfl_xor_sync(0xffffffffu, v, 1);
    if (sub == 0) {
        float pv = expf(v * SCALEF);
        p_out[(size_t)gw * 4 + h] = pv;
        atomicAdd(&den[((size_t)r * NN + d) * 4 + h], pv);
    }
}

// ---------------- edge pass 2: aggregate, head-mean folded, all relations ----
__global__ void edge_agg_all(const float* __restrict__ fs,
                             const int* __restrict__ src0,
                             const int* __restrict__ src1,
                             const int* __restrict__ src2,
                             const int* __restrict__ dst0,
                             const int* __restrict__ dst1,
                             const int* __restrict__ dst2,
                             const float* __restrict__ p,
                             const float* __restrict__ den,
                             float* __restrict__ hmean) {
    int gid = blockIdx.x * blockDim.x + threadIdx.x;
    int ge = gid >> 4;
    if (ge >= 3 * EE) return;
    int q = gid & 15;
    int r = ge / EE, e = ge - r * EE;
    const int* sp = (r == 0) ? src0 : (r == 1) ? src1 : src2;
    const int* dp = (r == 0) ? dst0 : (r == 1) ? dst1 : dst2;
    int s = sp[e], d = dp[e];
    float4 P = *reinterpret_cast<const float4*>(p + (size_t)ge * 4);
    float4 D = *reinterpret_cast<const float4*>(den + ((size_t)r * NN + d) * 4);
    float a0 = 0.25f * P.x / fmaxf(D.x, 1e-9f);
    float a1 = 0.25f * P.y / fmaxf(D.y, 1e-9f);
    float a2 = 0.25f * P.z / fmaxf(D.z, 1e-9f);
    float a3 = 0.25f * P.w / fmaxf(D.w, 1e-9f);
    const float4* ps = reinterpret_cast<const float4*>(fs + (size_t)s * FDR + r * 256);
    float4 f0 = ps[q], f1 = ps[16 + q], f2 = ps[32 + q], f3 = ps[48 + q];
    float vx = a0 * f0.x + a1 * f1.x + a2 * f2.x + a3 * f3.x;
    float vy = a0 * f0.y + a1 * f1.y + a2 * f2.y + a3 * f3.y;
    float vz = a0 * f0.z + a1 * f1.z + a2 * f2.z + a3 * f3.z;
    float vw = a0 * f0.w + a1 * f1.w + a2 * f2.w + a3 * f3.w;
    asm volatile("red.global.add.v4.f32 [%0], {%1,%2,%3,%4};"
                 :: "l"(hmean + (size_t)d * HD + q * 4),
                    "f"(vx), "f"(vy), "f"(vz), "f"(vw) : "memory");
}

// ---------------- batchnorm --------------------------------------------------
__global__ void bn_stats_kernel(const float* __restrict__ x,
                                float* __restrict__ bnstat) {
    int ch = threadIdx.x & 63;
    int rr = threadIdx.x >> 6;   // 0..3
    float s = 0.0f, s2 = 0.0f;
    for (int n = blockIdx.x * 4 + rr; n < NN; n += gridDim.x * 4) {
        float v = x[n * HD + ch];
        s += v; s2 += v * v;
    }
    __shared__ float sh[256], sh2[256];
    sh[threadIdx.x] = s; sh2[threadIdx.x] = s2;
    __syncthreads();
    if (rr == 0) {
        s  = sh[ch] + sh[64 + ch] + sh[128 + ch] + sh[192 + ch];
        s2 = sh2[ch] + sh2[64 + ch] + sh2[128 + ch] + sh2[192 + ch];
        atomicAdd(&bnstat[ch], s);
        atomicAdd(&bnstat[64 + ch], s2);
    }
}

__global__ void bn_norm_kernel(float* __restrict__ x,
                               const float* __restrict__ bnstat,
                               const float* __restrict__ gamma,
                               const float* __restrict__ beta) {
    int idx = blockIdx.x * blockDim.x + threadIdx.x;
    if (idx >= NN * HD) return;
    int ch = idx & 63;
    float mu = bnstat[ch] * (1.0f / NN);
    float var = bnstat[64 + ch] * (1.0f / NN) - mu * mu;
    float inv = rsqrtf(var + EPS_BN);
    x[idx] = gamma[ch] * (x[idx] - mu) * inv + beta[ch];
}

// ---------------- host orchestration -----------------------------------------
extern "C" void kernel_launch(void* const* d_in, const int* in_sizes, int n_in,
                              void* d_out, int out_size) {
    const float* x    = (const float*)d_in[0];
    const int* src0 = (const int*)d_in[1];
    const int* dst0 = (const int*)d_in[2];
    const int* src1 = (const int*)d_in[3];
    const int* dst1 = (const int*)d_in[4];
    const int* src2 = (const int*)d_in[5];
    const int* dst2 = (const int*)d_in[6];
    const float* Wsrc = (const float*)d_in[7];   // [2,3,64,256]
    const float* Wdst = (const float*)d_in[8];   // [2,3,64,256]
    const float* Wfc  = (const float*)d_in[9];   // [2,64,64]
    const float* bfc  = (const float*)d_in[10];  // [2,64]
    const float* gamma= (const float*)d_in[11];  // [2,64]
    const float* beta = (const float*)d_in[12];  // [2,64]
    const float* Wdim = (const float*)d_in[13];  // [64,256]
    const float* bdim = (const float*)d_in[14];  // [256]
    float* out = (float*)d_out;

    float *fs, *fd, *p, *den, *hmean, *h, *bnstat;
    cudaGetSymbolAddress((void**)&fs,    g_fs);
    cudaGetSymbolAddress((void**)&fd,    g_fd);
    cudaGetSymbolAddress((void**)&p,     g_p);
    cudaGetSymbolAddress((void**)&den,   g_den);
    cudaGetSymbolAddress((void**)&hmean, g_hmean);
    cudaGetSymbolAddress((void**)&h,     g_h);
    cudaGetSymbolAddress((void**)&bnstat,g_bnstat);

    cudaFuncSetAttribute(gemm_tf32s<0, 0>, cudaFuncAttributeMaxDynamicSharedMemorySize, GEMM_SMEM);
    cudaFuncSetAttribute(gemm_tf32s<1, 1>, cudaFuncAttributeMaxDynamicSharedMemorySize, GEMM_SMEM);
    cudaFuncSetAttribute(gemm_tf32s<1, 0>, cudaFuncAttributeMaxDynamicSharedMemorySize, GEMM_SMEM);

    const int mtiles = (NN + 127) / 128;            // 391
    const dim3 grid_proj(12, mtiles);               // NcC=768
    const dim3 grid_fc(1, mtiles);                  // NcC=64
    const dim3 grid_out(4, mtiles);                 // NcC=256
    const int sm_blocks  = 3 * EE / 8;              // warp per (rel,edge)
    const int agg_blocks = 3 * EE * 16 / 256;
    const int nhd_blocks = (NN * HD + 255) / 256;

    const float* hin = x;
    for (int l = 0; l < 2; l++) {
        const float* Ws = Wsrc + (size_t)l * 3 * 64 * 256;
        const float* Wd = Wdst + (size_t)l * 3 * 64 * 256;
        fill_kernel<<<1024, 256>>>(hmean, NN * HD, 0.0f);
        fill_kernel<<<512, 256>>>(den, 3 * NN * NH, 0.0f);
        gemm_tf32s<0, 0><<<grid_proj, 256, GEMM_SMEM>>>(hin, Ws, nullptr, fs, NN, FDR, 256);
        gemm_tf32s<0, 0><<<grid_proj, 256, GEMM_SMEM>>>(hin, Wd, nullptr, fd, NN, FDR, 256);
        edge_softmax_all<<<sm_blocks, 256>>>(fs, fd, src0, dst0, src1, dst1, src2, dst2, p, den);
        edge_agg_all<<<agg_blocks, 256>>>(fs, src0, src1, src2, dst0, dst1, dst2, p, den, hmean);
        gemm_tf32s<1, 1><<<grid_fc, 256, GEMM_SMEM>>>(hmean, Wfc + (size_t)l * 64 * 64,
                                                      bfc + l * 64, h, NN, HD, 64);
        fill_kernel<<<1, 128>>>(bnstat, 2 * HD, 0.0f);
        bn_stats_kernel<<<512, 256>>>(h, bnstat);
        bn_norm_kernel<<<nhd_blocks, 256>>>(h, bnstat, gamma + l * 64, beta + l * 64);
        hin = h;
    }
    gemm_tf32s<1, 0><<<grid_out, 256, GEMM_SMEM>>>(h, Wdim, bdim, out, NN, IND, 256);
    (void)in_sizes; (void)n_in; (void)out_size;
}

// round 6
// speedup vs baseline: 1.2456x; 1.2456x over previous
#include <cuda_runtime.h>
#include <cuda_bf16.h>
#include <math.h>

#define NN 50000
#define EE 250000
#define HD 64
#define NH 4
#define FDR 768         // 3 relations * 4 heads * 64
#define IND 256
#define SCALEF 0.125f   // 1/sqrt(64)
#define EPS_BN 1e-5f
#define PLD 36          // plane row stride in words (conflict-free: 4*gid+tig)

// ---------------- scratch (static device globals; no allocation) -------------
__device__ float g_fs[(size_t)NN * FDR];
__device__ float g_fd[(size_t)NN * FDR];
__device__ float g_p[3u * EE * NH];
__device__ float g_den[3 * NN * NH];
__device__ float g_hmean[NN * HD];
__device__ float g_h[NN * HD];
__device__ float g_bnstat[2 * HD];

// ---------------- fills -------------------------------------------------------
__global__ void fill_kernel(float* __restrict__ p, int n, float v) {
    int i = blockIdx.x * blockDim.x + threadIdx.x;
    int stride = gridDim.x * blockDim.x;
    for (; i < n; i += stride) p[i] = v;
}

// ---------------- bf16 split helpers -----------------------------------------
// x = b0 + b1 + eps, |eps| <~ 2^-18 |x|
__device__ __forceinline__ void bsplit(float x, unsigned short& b0, unsigned short& b1) {
    __nv_bfloat16 h0 = __float2bfloat16(x);
    b0 = __bfloat16_as_ushort(h0);
    b1 = __bfloat16_as_ushort(__float2bfloat16(x - __bfloat162float(h0)));
}
__device__ __forceinline__ unsigned pack2(unsigned short lo, unsigned short hi) {
    return (unsigned)lo | ((unsigned)hi << 16);
}
__device__ __forceinline__ void mma_bf16(float* c,
                                         unsigned a0, unsigned a1, unsigned a2, unsigned a3,
                                         unsigned b0, unsigned b1) {
    asm volatile("mma.sync.aligned.m16n8k16.row.col.f32.bf16.bf16.f32 "
                 "{%0,%1,%2,%3}, {%4,%5,%6,%7}, {%8,%9}, {%0,%1,%2,%3};"
                 : "+f"(c[0]), "+f"(c[1]), "+f"(c[2]), "+f"(c[3])
                 : "r"(a0), "r"(a1), "r"(a2), "r"(a3), "r"(b0), "r"(b1));
}

// ---------------- GEMM: C[M,NcC] = A[M,64] @ B-blocks (+bias)(+relu) ---------
// 64x64 block tile, 8 warps (4 row-groups x 2 col-groups), warp tile 16x32.
// bf16x3 compensated split: A0B0 + A0B1 + A1B0 with m16n8k16 bf16 MMAs.
// Planes: Ab[p][row][kpair] packed (b_p[2j], b_p[2j+1]); Bb[p][n][kpair].
// Stride 36 words -> fragment loads conflict-free (bank = 4*gid + tig).
template <int BIAS, int RELU>
__global__ void gemm_bf16x3(const float* __restrict__ A,
                            const float* __restrict__ B,
                            const float* __restrict__ bias,
                            float* __restrict__ C, int M, int NcC, int ldb) {
    __shared__ unsigned Ab[2][64][PLD];
    __shared__ unsigned Bb[2][64][PLD];

    const int bm = blockIdx.y * 64;
    const int bn = blockIdx.x * 64;
    const int tid = threadIdx.x;
    const float* Bblk = B + (size_t)(bn >> 8) * (64 * 256) + (bn & 255);

    // A tile: 64 rows x 16 k-quads
    for (int i = tid; i < 64 * 16; i += 256) {
        int r = i >> 4, q = i & 15;
        int gr = bm + r;
        float4 v = make_float4(0.f, 0.f, 0.f, 0.f);
        if (gr < M) v = *reinterpret_cast<const float4*>(&A[(size_t)gr * 64 + 4 * q]);
        unsigned short x0, x1, y0, y1, z0, z1, w0, w1;
        bsplit(v.x, x0, x1); bsplit(v.y, y0, y1);
        bsplit(v.z, z0, z1); bsplit(v.w, w0, w1);
        Ab[0][r][2 * q]     = pack2(x0, y0);
        Ab[0][r][2 * q + 1] = pack2(z0, w0);
        Ab[1][r][2 * q]     = pack2(x1, y1);
        Ab[1][r][2 * q + 1] = pack2(z1, w1);
    }
    // B tile: 32 k-pairs x 16 n-quads; transpose into [n][kpair] planes
    for (int i = tid; i < 32 * 16; i += 256) {
        int j = i >> 4, q = i & 15;
        float4 v0 = *reinterpret_cast<const float4*>(&Bblk[(size_t)(2 * j) * ldb + 4 * q]);
        float4 v1 = *reinterpret_cast<const float4*>(&Bblk[(size_t)(2 * j + 1) * ldb + 4 * q]);
        const float e0[4] = {v0.x, v0.y, v0.z, v0.w};
        const float e1[4] = {v1.x, v1.y, v1.z, v1.w};
#pragma unroll
        for (int c = 0; c < 4; c++) {
            unsigned short p0, p1, q0, q1;
            bsplit(e0[c], p0, p1);
            bsplit(e1[c], q0, q1);
            Bb[0][4 * q + c][j] = pack2(p0, q0);
            Bb[1][4 * q + c][j] = pack2(p1, q1);
        }
    }
    __syncthreads();

    const int warp = tid >> 5, lane = tid & 31;
    const int rowg = warp >> 1, colg = warp & 1;
    const int rbase = rowg * 16, cbase = colg * 32;
    const int gid = lane >> 2, tig = lane & 3;

    float acc[4][4];
#pragma unroll
    for (int nt = 0; nt < 4; nt++)
#pragma unroll
        for (int j = 0; j < 4; j++) acc[nt][j] = 0.0f;

#pragma unroll
    for (int kc = 0; kc < 4; kc++) {
        const int kb = kc * 8;
        unsigned a00 = Ab[0][rbase + gid][kb + tig];
        unsigned a01 = Ab[0][rbase + gid + 8][kb + tig];
        unsigned a02 = Ab[0][rbase + gid][kb + tig + 4];
        unsigned a03 = Ab[0][rbase + gid + 8][kb + tig + 4];
        unsigned a10 = Ab[1][rbase + gid][kb + tig];
        unsigned a11 = Ab[1][rbase + gid + 8][kb + tig];
        unsigned a12 = Ab[1][rbase + gid][kb + tig + 4];
        unsigned a13 = Ab[1][rbase + gid + 8][kb + tig + 4];
#pragma unroll
        for (int nt = 0; nt < 4; nt++) {
            int n = cbase + nt * 8 + gid;
            unsigned b00 = Bb[0][n][kb + tig];
            unsigned b01 = Bb[0][n][kb + tig + 4];
            unsigned b10 = Bb[1][n][kb + tig];
            unsigned b11 = Bb[1][n][kb + tig + 4];
            mma_bf16(acc[nt], a00, a01, a02, a03, b00, b01);
            mma_bf16(acc[nt], a00, a01, a02, a03, b10, b11);
            mma_bf16(acc[nt], a10, a11, a12, a13, b00, b01);
        }
    }

#pragma unroll
    for (int nt = 0; nt < 4; nt++) {
        int c = bn + cbase + nt * 8 + 2 * tig;
        float bb0 = 0.f, bb1 = 0.f;
        if (BIAS) { bb0 = bias[c]; bb1 = bias[c + 1]; }
#pragma unroll
        for (int half = 0; half < 2; half++) {
            int gr = bm + rbase + gid + half * 8;
            if (gr >= M) continue;
            float v0 = acc[nt][half * 2 + 0] + bb0;
            float v1 = acc[nt][half * 2 + 1] + bb1;
            if (RELU) { v0 = fmaxf(v0, 0.0f); v1 = fmaxf(v1, 0.0f); }
            *reinterpret_cast<float2*>(&C[(size_t)gr * NcC + c]) = make_float2(v0, v1);
        }
    }
}

// ---------------- edge pass 1: dot + exp + denominator (all 3 relations) -----
__global__ void edge_softmax_all(const float* __restrict__ fs,
                                 const float* __restrict__ fd,
                                 const int* __restrict__ src0, const int* __restrict__ dst0,
                                 const int* __restrict__ src1, const int* __restrict__ dst1,
                                 const int* __restrict__ src2, const int* __restrict__ dst2,
                                 float* __restrict__ p_out, float* __restrict__ den) {
    int gw = blockIdx.x * 8 + (threadIdx.x >> 5);
    if (gw >= 3 * EE) return;
    int r = gw / EE, e = gw - r * EE;
    const int* sp = (r == 0) ? src0 : (r == 1) ? src1 : src2;
    const int* dp = (r == 0) ? dst0 : (r == 1) ? dst1 : dst2;
    int s = sp[e], d = dp[e];
    int lane = threadIdx.x & 31;
    int h = lane >> 3, sub = lane & 7;
    const float4* ps = reinterpret_cast<const float4*>(fs + (size_t)s * FDR + r * 256 + h * 64) + sub * 2;
    const float4* pd = reinterpret_cast<const float4*>(fd + (size_t)d * FDR + r * 256 + h * 64) + sub * 2;
    float4 a0 = ps[0], a1 = ps[1];
    float4 b0 = pd[0], b1 = pd[1];
    float v = a0.x * b0.x + a0.y * b0.y + a0.z * b0.z + a0.w * b0.w +
              a1.x * b1.x + a1.y * b1.y + a1.z * b1.z + a1.w * b1.w;
    v += __shfl_xor_sync(0xffffffffu, v, 4);
    v += __shfl_xor_sync(0xffffffffu, v, 2);
    v += __shfl_xor_sync(0xffffffffu, v, 1);
    if (sub == 0) {
        float pv = expf(v * SCALEF);
        p_out[(size_t)gw * 4 + h] = pv;
        atomicAdd(&den[((size_t)r * NN + d) * 4 + h], pv);
    }
}

// ---------------- edge pass 2: aggregate, head-mean folded, all relations ----
__global__ void edge_agg_all(const float* __restrict__ fs,
                             const int* __restrict__ src0,
                             const int* __restrict__ src1,
                             const int* __restrict__ src2,
                             const int* __restrict__ dst0,
                             const int* __restrict__ dst1,
                             const int* __restrict__ dst2,
                             const float* __restrict__ p,
                             const float* __restrict__ den,
                             float* __restrict__ hmean) {
    int gid = blockIdx.x * blockDim.x + threadIdx.x;
    int ge = gid >> 4;
    if (ge >= 3 * EE) return;
    int q = gid & 15;
    int r = ge / EE, e = ge - r * EE;
    const int* sp = (r == 0) ? src0 : (r == 1) ? src1 : src2;
    const int* dp = (r == 0) ? dst0 : (r == 1) ? dst1 : dst2;
    int s = sp[e], d = dp[e];
    float4 P = *reinterpret_cast<const float4*>(p + (size_t)ge * 4);
    float4 D = *reinterpret_cast<const float4*>(den + ((size_t)r * NN + d) * 4);
    float a0 = 0.25f * P.x / fmaxf(D.x, 1e-9f);
    float a1 = 0.25f * P.y / fmaxf(D.y, 1e-9f);
    float a2 = 0.25f * P.z / fmaxf(D.z, 1e-9f);
    float a3 = 0.25f * P.w / fmaxf(D.w, 1e-9f);
    const float4* ps = reinterpret_cast<const float4*>(fs + (size_t)s * FDR + r * 256);
    float4 f0 = ps[q], f1 = ps[16 + q], f2 = ps[32 + q], f3 = ps[48 + q];
    float vx = a0 * f0.x + a1 * f1.x + a2 * f2.x + a3 * f3.x;
    float vy = a0 * f0.y + a1 * f1.y + a2 * f2.y + a3 * f3.y;
    float vz = a0 * f0.z + a1 * f1.z + a2 * f2.z + a3 * f3.z;
    float vw = a0 * f0.w + a1 * f1.w + a2 * f2.w + a3 * f3.w;
    asm volatile("red.global.add.v4.f32 [%0], {%1,%2,%3,%4};"
                 :: "l"(hmean + (size_t)d * HD + q * 4),
                    "f"(vx), "f"(vy), "f"(vz), "f"(vw) : "memory");
}

// ---------------- batchnorm --------------------------------------------------
__global__ void bn_stats_kernel(const float* __restrict__ x,
                                float* __restrict__ bnstat) {
    int ch = threadIdx.x & 63;
    int rr = threadIdx.x >> 6;   // 0..3
    float s = 0.0f, s2 = 0.0f;
    for (int n = blockIdx.x * 4 + rr; n < NN; n += gridDim.x * 4) {
        float v = x[n * HD + ch];
        s += v; s2 += v * v;
    }
    __shared__ float sh[256], sh2[256];
    sh[threadIdx.x] = s; sh2[threadIdx.x] = s2;
    __syncthreads();
    if (rr == 0) {
        s  = sh[ch] + sh[64 + ch] + sh[128 + ch] + sh[192 + ch];
        s2 = sh2[ch] + sh2[64 + ch] + sh2[128 + ch] + sh2[192 + ch];
        atomicAdd(&bnstat[ch], s);
        atomicAdd(&bnstat[64 + ch], s2);
    }
}

__global__ void bn_norm_kernel(float* __restrict__ x,
                               const float* __restrict__ bnstat,
                               const float* __restrict__ gamma,
                               const float* __restrict__ beta) {
    int idx = blockIdx.x * blockDim.x + threadIdx.x;
    if (idx >= NN * HD) return;
    int ch = idx & 63;
    float mu = bnstat[ch] * (1.0f / NN);
    float var = bnstat[64 + ch] * (1.0f / NN) - mu * mu;
    float inv = rsqrtf(var + EPS_BN);
    x[idx] = gamma[ch] * (x[idx] - mu) * inv + beta[ch];
}

// ---------------- host orchestration -----------------------------------------
extern "C" void kernel_launch(void* const* d_in, const int* in_sizes, int n_in,
                              void* d_out, int out_size) {
    const float* x    = (const float*)d_in[0];
    const int* src0 = (const int*)d_in[1];
    const int* dst0 = (const int*)d_in[2];
    const int* src1 = (const int*)d_in[3];
    const int* dst1 = (const int*)d_in[4];
    const int* src2 = (const int*)d_in[5];
    const int* dst2 = (const int*)d_in[6];
    const float* Wsrc = (const float*)d_in[7];   // [2,3,64,256]
    const float* Wdst = (const float*)d_in[8];   // [2,3,64,256]
    const float* Wfc  = (const float*)d_in[9];   // [2,64,64]
    const float* bfc  = (const float*)d_in[10];  // [2,64]
    const float* gamma= (const float*)d_in[11];  // [2,64]
    const float* beta = (const float*)d_in[12];  // [2,64]
    const float* Wdim = (const float*)d_in[13];  // [64,256]
    const float* bdim = (const float*)d_in[14];  // [256]
    float* out = (float*)d_out;

    float *fs, *fd, *p, *den, *hmean, *h, *bnstat;
    cudaGetSymbolAddress((void**)&fs,    g_fs);
    cudaGetSymbolAddress((void**)&fd,    g_fd);
    cudaGetSymbolAddress((void**)&p,     g_p);
    cudaGetSymbolAddress((void**)&den,   g_den);
    cudaGetSymbolAddress((void**)&hmean, g_hmean);
    cudaGetSymbolAddress((void**)&h,     g_h);
    cudaGetSymbolAddress((void**)&bnstat,g_bnstat);

    const int mtiles = (NN + 63) / 64;              // 782
    const dim3 grid_proj(12, mtiles);               // NcC=768
    const dim3 grid_fc(1, mtiles);                  // NcC=64
    const dim3 grid_out(4, mtiles);                 // NcC=256
    const int sm_blocks  = 3 * EE / 8;              // warp per (rel,edge)
    const int agg_blocks = 3 * EE * 16 / 256;
    const int nhd_blocks = (NN * HD + 255) / 256;

    const float* hin = x;
    for (int l = 0; l < 2; l++) {
        const float* Ws = Wsrc + (size_t)l * 3 * 64 * 256;
        const float* Wd = Wdst + (size_t)l * 3 * 64 * 256;
        fill_kernel<<<1024, 256>>>(hmean, NN * HD, 0.0f);
        fill_kernel<<<512, 256>>>(den, 3 * NN * NH, 0.0f);
        gemm_bf16x3<0, 0><<<grid_proj, 256>>>(hin, Ws, nullptr, fs, NN, FDR, 256);
        gemm_bf16x3<0, 0><<<grid_proj, 256>>>(hin, Wd, nullptr, fd, NN, FDR, 256);
        edge_softmax_all<<<sm_blocks, 256>>>(fs, fd, src0, dst0, src1, dst1, src2, dst2, p, den);
        edge_agg_all<<<agg_blocks, 256>>>(fs, src0, src1, src2, dst0, dst1, dst2, p, den, hmean);
        gemm_bf16x3<1, 1><<<grid_fc, 256>>>(hmean, Wfc + (size_t)l * 64 * 64,
                                            bfc + l * 64, h, NN, HD, 64);
        fill_kernel<<<1, 128>>>(bnstat, 2 * HD, 0.0f);
        bn_stats_kernel<<<512, 256>>>(h, bnstat);
        bn_norm_kernel<<<nhd_blocks, 256>>>(h, bnstat, gamma + l * 64, beta + l * 64);
        hin = h;
    }
    gemm_bf16x3<1, 0><<<grid_out, 256>>>(h, Wdim, bdim, out, NN, IND, 256);
    (void)in_sizes; (void)n_in; (void)out_size;
}

// round 8
// speedup vs baseline: 1.2921x; 1.0373x over previous
#include <cuda_runtime.h>
#include <cuda_bf16.h>
#include <math.h>

#define NN 50000
#define EE 250000
#define HD 64
#define NH 4
#define FDR 768         // 3 relations * 4 heads * 64
#define IND 256
#define SCALEF 0.125f   // 1/sqrt(64)
#define EPS_BN 1e-5f
#define PLD 36          // plane row stride in words (conflict-free: 4*gid+tig)

// ---------------- scratch (static device globals; no allocation) -------------
__device__ float g_fs[(size_t)NN * FDR];
__device__ float g_fd[(size_t)NN * FDR];
__device__ float g_p[3u * EE * NH];
__device__ float g_den[3 * NN * NH];
__device__ float g_hmean[NN * HD];
__device__ float g_h[NN * HD];
__device__ float g_bnstat[2 * HD];

// ---------------- fills -------------------------------------------------------
__global__ void fill_kernel(float* __restrict__ p, int n, float v) {
    int i = blockIdx.x * blockDim.x + threadIdx.x;
    int stride = gridDim.x * blockDim.x;
    for (; i < n; i += stride) p[i] = v;
}

// ---------------- bf16 split helpers -----------------------------------------
__device__ __forceinline__ void bsplit(float x, unsigned short& b0, unsigned short& b1) {
    __nv_bfloat16 h0 = __float2bfloat16(x);
    b0 = __bfloat16_as_ushort(h0);
    b1 = __bfloat16_as_ushort(__float2bfloat16(x - __bfloat162float(h0)));
}
__device__ __forceinline__ unsigned pack2(unsigned short lo, unsigned short hi) {
    return (unsigned)lo | ((unsigned)hi << 16);
}
__device__ __forceinline__ void mma_bf16(float* c,
                                         unsigned a0, unsigned a1, unsigned a2, unsigned a3,
                                         unsigned b0, unsigned b1) {
    asm volatile("mma.sync.aligned.m16n8k16.row.col.f32.bf16.bf16.f32 "
                 "{%0,%1,%2,%3}, {%4,%5,%6,%7}, {%8,%9}, {%0,%1,%2,%3};"
                 : "+f"(c[0]), "+f"(c[1]), "+f"(c[2]), "+f"(c[3])
                 : "r"(a0), "r"(a1), "r"(a2), "r"(a3), "r"(b0), "r"(b1));
}

// ---------------- GEMM: C[M,·] = A[M,64] @ B-blocks (+bias)(+relu) -----------
// 64x64 block tile, 128 threads = 4 warps (2 rowg x 2 colg), warp tile 32x32.
// bf16x3 compensated split, m16n8k16 MMAs. 1.33 LDS per MMA.
// DUAL=1: columns [0,768) -> Bsrc/Cs, [768,1536) -> Bdst/Cd (NcC=768 each).
template <int DUAL, int BIAS, int RELU>
__global__ void gemm_bf16x3(const float* __restrict__ A,
                            const float* __restrict__ Bsrc,
                            const float* __restrict__ Bdst,
                            const float* __restrict__ bias,
                            float* __restrict__ Cs,
                            float* __restrict__ Cd,
                            int M, int NcC, int ldb) {
    __shared__ unsigned Ab[2][64][PLD];
    __shared__ unsigned Bb[2][64][PLD];

    const int bm = blockIdx.y * 64;
    int bn = blockIdx.x * 64;
    const int tid = threadIdx.x;

    const float* Bsel = Bsrc;
    float* Csel = Cs;
    if (DUAL && bn >= 768) { Bsel = Bdst; Csel = Cd; bn -= 768; }
    const float* Bblk = Bsel + (size_t)(bn >> 8) * (64 * 256) + (bn & 255);

    // A tile: 64 rows x 16 k-quads
    for (int i = tid; i < 64 * 16; i += 128) {
        int r = i >> 4, q = i & 15;
        int gr = bm + r;
        float4 v = make_float4(0.f, 0.f, 0.f, 0.f);
        if (gr < M) v = *reinterpret_cast<const float4*>(&A[(size_t)gr * 64 + 4 * q]);
        unsigned short x0, x1, y0, y1, z0, z1, w0, w1;
        bsplit(v.x, x0, x1); bsplit(v.y, y0, y1);
        bsplit(v.z, z0, z1); bsplit(v.w, w0, w1);
        Ab[0][r][2 * q]     = pack2(x0, y0);
        Ab[0][r][2 * q + 1] = pack2(z0, w0);
        Ab[1][r][2 * q]     = pack2(x1, y1);
        Ab[1][r][2 * q + 1] = pack2(z1, w1);
    }
    // B tile: 32 k-pairs x 16 n-quads; transpose into [n][kpair] planes
    for (int i = tid; i < 32 * 16; i += 128) {
        int j = i >> 4, q = i & 15;
        float4 v0 = *reinterpret_cast<const float4*>(&Bblk[(size_t)(2 * j) * ldb + 4 * q]);
        float4 v1 = *reinterpret_cast<const float4*>(&Bblk[(size_t)(2 * j + 1) * ldb + 4 * q]);
        const float e0[4] = {v0.x, v0.y, v0.z, v0.w};
        const float e1[4] = {v1.x, v1.y, v1.z, v1.w};
#pragma unroll
        for (int c = 0; c < 4; c++) {
            unsigned short p0, p1, q0, q1;
            bsplit(e0[c], p0, p1);
            bsplit(e1[c], q0, q1);
            Bb[0][4 * q + c][j] = pack2(p0, q0);
            Bb[1][4 * q + c][j] = pack2(p1, q1);
        }
    }
    __syncthreads();

    const int warp = tid >> 5, lane = tid & 31;
    const int rowg = warp >> 1, colg = warp & 1;
    const int rbase = rowg * 32, cbase = colg * 32;
    const int gid = lane >> 2, tig = lane & 3;

    float acc[2][4][4];
#pragma unroll
    for (int mb = 0; mb < 2; mb++)
#pragma unroll
        for (int nt = 0; nt < 4; nt++)
#pragma unroll
            for (int j = 0; j < 4; j++) acc[mb][nt][j] = 0.0f;

#pragma unroll
    for (int kc = 0; kc < 4; kc++) {
        const int kb = kc * 8;
        unsigned a0[2][4], a1[2][4];
#pragma unroll
        for (int mb = 0; mb < 2; mb++) {
            const int r0 = rbase + mb * 16 + gid;
            a0[mb][0] = Ab[0][r0][kb + tig];
            a0[mb][1] = Ab[0][r0 + 8][kb + tig];
            a0[mb][2] = Ab[0][r0][kb + tig + 4];
            a0[mb][3] = Ab[0][r0 + 8][kb + tig + 4];
            a1[mb][0] = Ab[1][r0][kb + tig];
            a1[mb][1] = Ab[1][r0 + 8][kb + tig];
            a1[mb][2] = Ab[1][r0][kb + tig + 4];
            a1[mb][3] = Ab[1][r0 + 8][kb + tig + 4];
        }
#pragma unroll
        for (int nt = 0; nt < 4; nt++) {
            int n = cbase + nt * 8 + gid;
            unsigned b00 = Bb[0][n][kb + tig];
            unsigned b01 = Bb[0][n][kb + tig + 4];
            unsigned b10 = Bb[1][n][kb + tig];
            unsigned b11 = Bb[1][n][kb + tig + 4];
#pragma unroll
            for (int mb = 0; mb < 2; mb++) {
                mma_bf16(acc[mb][nt], a0[mb][0], a0[mb][1], a0[mb][2], a0[mb][3], b00, b01);
                mma_bf16(acc[mb][nt], a0[mb][0], a0[mb][1], a0[mb][2], a0[mb][3], b10, b11);
                mma_bf16(acc[mb][nt], a1[mb][0], a1[mb][1], a1[mb][2], a1[mb][3], b00, b01);
            }
        }
    }

#pragma unroll
    for (int mb = 0; mb < 2; mb++)
#pragma unroll
        for (int nt = 0; nt < 4; nt++) {
            int c = cbase + nt * 8 + 2 * tig;
            float bb0 = 0.f, bb1 = 0.f;
            if (BIAS) { bb0 = bias[bn + c]; bb1 = bias[bn + c + 1]; }
#pragma unroll
            for (int half = 0; half < 2; half++) {
                int gr = bm + rbase + mb * 16 + gid + half * 8;
                if (gr >= M) continue;
                float v0 = acc[mb][nt][half * 2 + 0] + bb0;
                float v1 = acc[mb][nt][half * 2 + 1] + bb1;
                if (RELU) { v0 = fmaxf(v0, 0.0f); v1 = fmaxf(v1, 0.0f); }
                *reinterpret_cast<float2*>(&Csel[(size_t)gr * NcC + bn + c]) = make_float2(v0, v1);
            }
        }
}

// ---------------- edge pass 1: dot + exp + denominator (all 3 relations) -----
__global__ void edge_softmax_all(const float* __restrict__ fs,
                                 const float* __restrict__ fd,
                                 const int* __restrict__ src0, const int* __restrict__ dst0,
                                 const int* __restrict__ src1, const int* __restrict__ dst1,
                                 const int* __restrict__ src2, const int* __restrict__ dst2,
                                 float* __restrict__ p_out, float* __restrict__ den) {
    int gw = blockIdx.x * 8 + (threadIdx.x >> 5);
    if (gw >= 3 * EE) return;
    int r = gw / EE, e = gw - r * EE;
    const int* sp = (r == 0) ? src0 : (r == 1) ? src1 : src2;
    const int* dp = (r == 0) ? dst0 : (r == 1) ? dst1 : dst2;
    int s = sp[e], d = dp[e];
    int lane = threadIdx.x & 31;
    int h = lane >> 3, sub = lane & 7;
    const float4* ps = reinterpret_cast<const float4*>(fs + (size_t)s * FDR + r * 256 + h * 64) + sub * 2;
    const float4* pd = reinterpret_cast<const float4*>(fd + (size_t)d * FDR + r * 256 + h * 64) + sub * 2;
    float4 a0 = ps[0], a1 = ps[1];
    float4 b0 = pd[0], b1 = pd[1];
    float v = a0.x * b0.x + a0.y * b0.y + a0.z * b0.z + a0.w * b0.w +
              a1.x * b1.x + a1.y * b1.y + a1.z * b1.z + a1.w * b1.w;
    v += __shfl_xor_sync(0xffffffffu, v, 4);
    v += __shfl_xor_sync(0xffffffffu, v, 2);
    v += __shfl_xor_sync(0xffffffffu, v, 1);
    if (sub == 0) {
        float pv = expf(v * SCALEF);
        p_out[(size_t)gw * 4 + h] = pv;
        atomicAdd(&den[((size_t)r * NN + d) * 4 + h], pv);
    }
}

// ---------------- edge pass 2: aggregate, head-mean folded, all relations ----
__global__ void edge_agg_all(const float* __restrict__ fs,
                             const int* __restrict__ src0,
                             const int* __restrict__ src1,
                             const int* __restrict__ src2,
                             const int* __restrict__ dst0,
                             const int* __restrict__ dst1,
                             const int* __restrict__ dst2,
                             const float* __restrict__ p,
                             const float* __restrict__ den,
                             float* __restrict__ hmean) {
    int gid = blockIdx.x * blockDim.x + threadIdx.x;
    int ge = gid >> 4;
    if (ge >= 3 * EE) return;
    int q = gid & 15;
    int r = ge / EE, e = ge - r * EE;
    const int* sp = (r == 0) ? src0 : (r == 1) ? src1 : src2;
    const int* dp = (r == 0) ? dst0 : (r == 1) ? dst1 : dst2;
    int s = sp[e], d = dp[e];
    float4 P = *reinterpret_cast<const float4*>(p + (size_t)ge * 4);
    float4 D = *reinterpret_cast<const float4*>(den + ((size_t)r * NN + d) * 4);
    float a0 = 0.25f * P.x / fmaxf(D.x, 1e-9f);
    float a1 = 0.25f * P.y / fmaxf(D.y, 1e-9f);
    float a2 = 0.25f * P.z / fmaxf(D.z, 1e-9f);
    float a3 = 0.25f * P.w / fmaxf(D.w, 1e-9f);
    const float4* ps = reinterpret_cast<const float4*>(fs + (size_t)s * FDR + r * 256);
    float4 f0 = ps[q], f1 = ps[16 + q], f2 = ps[32 + q], f3 = ps[48 + q];
    float vx = a0 * f0.x + a1 * f1.x + a2 * f2.x + a3 * f3.x;
    float vy = a0 * f0.y + a1 * f1.y + a2 * f2.y + a3 * f3.y;
    float vz = a0 * f0.z + a1 * f1.z + a2 * f2.z + a3 * f3.z;
    float vw = a0 * f0.w + a1 * f1.w + a2 * f2.w + a3 * f3.w;
    asm volatile("red.global.add.v4.f32 [%0], {%1,%2,%3,%4};"
                 :: "l"(hmean + (size_t)d * HD + q * 4),
                    "f"(vx), "f"(vy), "f"(vz), "f"(vw) : "memory");
}

// ---------------- batchnorm --------------------------------------------------
__global__ void bn_stats_kernel(const float* __restrict__ x,
                                float* __restrict__ bnstat) {
    int ch = threadIdx.x & 63;
    int rr = threadIdx.x >> 6;   // 0..3
    float s = 0.0f, s2 = 0.0f;
    for (int n = blockIdx.x * 4 + rr; n < NN; n += gridDim.x * 4) {
        float v = x[n * HD + ch];
        s += v; s2 += v * v;
    }
    __shared__ float sh[256], sh2[256];
    sh[threadIdx.x] = s; sh2[threadIdx.x] = s2;
    __syncthreads();
    if (rr == 0) {
        s  = sh[ch] + sh[64 + ch] + sh[128 + ch] + sh[192 + ch];
        s2 = sh2[ch] + sh2[64 + ch] + sh2[128 + ch] + sh2[192 + ch];
        atomicAdd(&bnstat[ch], s);
        atomicAdd(&bnstat[64 + ch], s2);
    }
}

__global__ void bn_norm_kernel(float* __restrict__ x,
                               const float* __restrict__ bnstat,
                               const float* __restrict__ gamma,
                               const float* __restrict__ beta) {
    int idx = blockIdx.x * blockDim.x + threadIdx.x;
    if (idx >= NN * HD) return;
    int ch = idx & 63;
    float mu = bnstat[ch] * (1.0f / NN);
    float var = bnstat[64 + ch] * (1.0f / NN) - mu * mu;
    float inv = rsqrtf(var + EPS_BN);
    x[idx] = gamma[ch] * (x[idx] - mu) * inv + beta[ch];
}

// ---------------- host orchestration -----------------------------------------
extern "C" void kernel_launch(void* const* d_in, const int* in_sizes, int n_in,
                              void* d_out, int out_size) {
    const float* x    = (const float*)d_in[0];
    const int* src0 = (const int*)d_in[1];
    const int* dst0 = (const int*)d_in[2];
    const int* src1 = (const int*)d_in[3];
    const int* dst1 = (const int*)d_in[4];
    const int* src2 = (const int*)d_in[5];
    const int* dst2 = (const int*)d_in[6];
    const float* Wsrc = (const float*)d_in[7];   // [2,3,64,256]
    const float* Wdst = (const float*)d_in[8];   // [2,3,64,256]
    const float* Wfc  = (const float*)d_in[9];   // [2,64,64]
    const float* bfc  = (const float*)d_in[10];  // [2,64]
    const float* gamma= (const float*)d_in[11];  // [2,64]
    const float* beta = (const float*)d_in[12];  // [2,64]
    const float* Wdim = (const float*)d_in[13];  // [64,256]
    const float* bdim = (const float*)d_in[14];  // [256]
    float* out = (float*)d_out;

    float *fs, *fd, *p, *den, *hmean, *h, *bnstat;
    cudaGetSymbolAddress((void**)&fs,    g_fs);
    cudaGetSymbolAddress((void**)&fd,    g_fd);
    cudaGetSymbolAddress((void**)&p,     g_p);
    cudaGetSymbolAddress((void**)&den,   g_den);
    cudaGetSymbolAddress((void**)&hmean, g_hmean);
    cudaGetSymbolAddress((void**)&h,     g_h);
    cudaGetSymbolAddress((void**)&bnstat,g_bnstat);

    const int mtiles = (NN + 63) / 64;              // 782
    const dim3 grid_proj(24, mtiles);               // dual: fs cols + fd cols
    const dim3 grid_fc(1, mtiles);                  // NcC=64
    const dim3 grid_out(4, mtiles);                 // NcC=256
    const int sm_blocks  = 3 * EE / 8;              // warp per (rel,edge)
    const int agg_blocks = 3 * EE * 16 / 256;
    const int nhd_blocks = (NN * HD + 255) / 256;

    const float* hin = x;
    for (int l = 0; l < 2; l++) {
        const float* Ws = Wsrc + (size_t)l * 3 * 64 * 256;
        const float* Wd = Wdst + (size_t)l * 3 * 64 * 256;
        fill_kernel<<<1024, 256>>>(hmean, NN * HD, 0.0f);
        fill_kernel<<<512, 256>>>(den, 3 * NN * NH, 0.0f);
        gemm_bf16x3<1, 0, 0><<<grid_proj, 128>>>(hin, Ws, Wd, nullptr, fs, fd, NN, FDR, 256);
        edge_softmax_all<<<sm_blocks, 256>>>(fs, fd, src0, dst0, src1, dst1, src2, dst2, p, den);
        edge_agg_all<<<agg_blocks, 256>>>(fs, src0, src1, src2, dst0, dst1, dst2, p, den, hmean);
        gemm_bf16x3<0, 1, 1><<<grid_fc, 128>>>(hmean, Wfc + (size_t)l * 64 * 64, nullptr,
                                               bfc + l * 64, h, nullptr, NN, HD, 64);
        fill_kernel<<<1, 128>>>(bnstat, 2 * HD, 0.0f);
        bn_stats_kernel<<<512, 256>>>(h, bnstat);
        bn_norm_kernel<<<nhd_blocks, 256>>>(h, bnstat, gamma + l * 64, beta + l * 64);
        hin = h;
    }
    gemm_bf16x3<0, 1, 0><<<grid_out, 128>>>(h, Wdim, nullptr, bdim, out, nullptr, NN, IND, 256);
    (void)in_sizes; (void)n_in; (void)out_size;
}

// round 10
// speedup vs baseline: 1.4836x; 1.1482x over previous
#include <cuda_runtime.h>
#include <cuda_bf16.h>
#include <math.h>

#define NN 50000
#define EE 250000
#define HD 64
#define NH 4
#define FDR 768         // 3 relations * 4 heads * 64
#define IND 256
#define SCALEF 0.125f   // 1/sqrt(64)
#define EPS_BN 1e-5f
#define PLD 36          // plane row stride in words (conflict-free: 4*gid+tig)
#define NSEG (3 * NN)   // CSR segments

// ---------------- scratch (static device globals; no allocation) -------------
__device__ float g_fs[(size_t)NN * FDR];
__device__ float g_fd[(size_t)NN * FDR];
__device__ float g_hmean[NN * HD];
__device__ float g_h[NN * HD];
__device__ float g_bnstat[2 * HD];
__device__ int   g_cnt[NSEG];
__device__ int   g_rowptr[NSEG];
__device__ int   g_cursor[NSEG];
__device__ int   g_bsum[256];
__device__ int   g_csr[3 * EE];

// ---------------- fills -------------------------------------------------------
__global__ void fill_kernel(float* __restrict__ p, int n, float v) {
    int i = blockIdx.x * blockDim.x + threadIdx.x;
    int stride = gridDim.x * blockDim.x;
    for (; i < n; i += stride) p[i] = v;
}
__global__ void filli_kernel(int* __restrict__ p, int n, int v) {
    int i = blockIdx.x * blockDim.x + threadIdx.x;
    int stride = gridDim.x * blockDim.x;
    for (; i < n; i += stride) p[i] = v;
}

// ---------------- CSR build ---------------------------------------------------
__global__ void hist_kernel(const int* __restrict__ d0, const int* __restrict__ d1,
                            const int* __restrict__ d2, int* __restrict__ cnt) {
    int i = blockIdx.x * blockDim.x + threadIdx.x;
    if (i >= 3 * EE) return;
    int r = i / EE, e = i - r * EE;
    const int* dp = (r == 0) ? d0 : (r == 1) ? d1 : d2;
    atomicAdd(&cnt[r * NN + dp[e]], 1);
}

__global__ void scan_block(const int* __restrict__ in, int* __restrict__ out,
                           int* __restrict__ bsum, int n) {
    __shared__ int sh[1024];
    int gid = blockIdx.x * 1024 + threadIdx.x;
    int v = (gid < n) ? in[gid] : 0;
    sh[threadIdx.x] = v;
    __syncthreads();
    for (int off = 1; off < 1024; off <<= 1) {
        int t = (threadIdx.x >= off) ? sh[threadIdx.x - off] : 0;
        __syncthreads();
        sh[threadIdx.x] += t;
        __syncthreads();
    }
    if (gid < n) out[gid] = sh[threadIdx.x] - v;   // exclusive
    if (threadIdx.x == 1023) bsum[blockIdx.x] = sh[1023];
}

__global__ void scan_top(int* __restrict__ bsum, int nb) {
    if (blockIdx.x == 0 && threadIdx.x == 0) {
        int acc = 0;
        for (int i = 0; i < nb; i++) { int t = bsum[i]; bsum[i] = acc; acc += t; }
    }
}

__global__ void add_off(int* __restrict__ out, const int* __restrict__ bsum, int n) {
    int gid = blockIdx.x * 1024 + threadIdx.x;
    if (gid < n) out[gid] += bsum[blockIdx.x];
}

__global__ void copy_kernel(const int* __restrict__ a, int* __restrict__ b, int n) {
    int i = blockIdx.x * blockDim.x + threadIdx.x;
    if (i < n) b[i] = a[i];
}

__global__ void scatter_kernel(const int* __restrict__ s0, const int* __restrict__ d0,
                               const int* __restrict__ s1, const int* __restrict__ d1,
                               const int* __restrict__ s2, const int* __restrict__ d2,
                               int* __restrict__ cursor, int* __restrict__ csr) {
    int i = blockIdx.x * blockDim.x + threadIdx.x;
    if (i >= 3 * EE) return;
    int r = i / EE, e = i - r * EE;
    const int* sp = (r == 0) ? s0 : (r == 1) ? s1 : s2;
    const int* dp = (r == 0) ? d0 : (r == 1) ? d1 : d2;
    int pos = atomicAdd(&cursor[r * NN + dp[e]], 1);
    csr[pos] = sp[e];
}

// ---------------- bf16 split helpers -----------------------------------------
__device__ __forceinline__ void bsplit(float x, unsigned short& b0, unsigned short& b1) {
    __nv_bfloat16 h0 = __float2bfloat16(x);
    b0 = __bfloat16_as_ushort(h0);
    b1 = __bfloat16_as_ushort(__float2bfloat16(x - __bfloat162float(h0)));
}
__device__ __forceinline__ unsigned pack2(unsigned short lo, unsigned short hi) {
    return (unsigned)lo | ((unsigned)hi << 16);
}
__device__ __forceinline__ void mma_bf16(float* c,
                                         unsigned a0, unsigned a1, unsigned a2, unsigned a3,
                                         unsigned b0, unsigned b1) {
    asm volatile("mma.sync.aligned.m16n8k16.row.col.f32.bf16.bf16.f32 "
                 "{%0,%1,%2,%3}, {%4,%5,%6,%7}, {%8,%9}, {%0,%1,%2,%3};"
                 : "+f"(c[0]), "+f"(c[1]), "+f"(c[2]), "+f"(c[3])
                 : "r"(a0), "r"(a1), "r"(a2), "r"(a3), "r"(b0), "r"(b1));
}

// ---------------- GEMM (unchanged from R7: 64x64 tile, 4 warps of 32x32) -----
template <int DUAL, int BIAS, int RELU>
__global__ void gemm_bf16x3(const float* __restrict__ A,
                            const float* __restrict__ Bsrc,
                            const float* __restrict__ Bdst,
                            const float* __restrict__ bias,
                            float* __restrict__ Cs,
                            float* __restrict__ Cd,
                            int M, int NcC, int ldb) {
    __shared__ unsigned Ab[2][64][PLD];
    __shared__ unsigned Bb[2][64][PLD];

    const int bm = blockIdx.y * 64;
    int bn = blockIdx.x * 64;
    const int tid = threadIdx.x;

    const float* Bsel = Bsrc;
    float* Csel = Cs;
    if (DUAL && bn >= 768) { Bsel = Bdst; Csel = Cd; bn -= 768; }
    const float* Bblk = Bsel + (size_t)(bn >> 8) * (64 * 256) + (bn & 255);

    for (int i = tid; i < 64 * 16; i += 128) {
        int r = i >> 4, q = i & 15;
        int gr = bm + r;
        float4 v = make_float4(0.f, 0.f, 0.f, 0.f);
        if (gr < M) v = *reinterpret_cast<const float4*>(&A[(size_t)gr * 64 + 4 * q]);
        unsigned short x0, x1, y0, y1, z0, z1, w0, w1;
        bsplit(v.x, x0, x1); bsplit(v.y, y0, y1);
        bsplit(v.z, z0, z1); bsplit(v.w, w0, w1);
        Ab[0][r][2 * q]     = pack2(x0, y0);
        Ab[0][r][2 * q + 1] = pack2(z0, w0);
        Ab[1][r][2 * q]     = pack2(x1, y1);
        Ab[1][r][2 * q + 1] = pack2(z1, w1);
    }
    for (int i = tid; i < 32 * 16; i += 128) {
        int j = i >> 4, q = i & 15;
        float4 v0 = *reinterpret_cast<const float4*>(&Bblk[(size_t)(2 * j) * ldb + 4 * q]);
        float4 v1 = *reinterpret_cast<const float4*>(&Bblk[(size_t)(2 * j + 1) * ldb + 4 * q]);
        const float e0[4] = {v0.x, v0.y, v0.z, v0.w};
        const float e1[4] = {v1.x, v1.y, v1.z, v1.w};
#pragma unroll
        for (int c = 0; c < 4; c++) {
            unsigned short p0, p1, q0, q1;
            bsplit(e0[c], p0, p1);
            bsplit(e1[c], q0, q1);
            Bb[0][4 * q + c][j] = pack2(p0, q0);
            Bb[1][4 * q + c][j] = pack2(p1, q1);
        }
    }
    __syncthreads();

    const int warp = tid >> 5, lane = tid & 31;
    const int rowg = warp >> 1, colg = warp & 1;
    const int rbase = rowg * 32, cbase = colg * 32;
    const int gid = lane >> 2, tig = lane & 3;

    float acc[2][4][4];
#pragma unroll
    for (int mb = 0; mb < 2; mb++)
#pragma unroll
        for (int nt = 0; nt < 4; nt++)
#pragma unroll
            for (int j = 0; j < 4; j++) acc[mb][nt][j] = 0.0f;

#pragma unroll
    for (int kc = 0; kc < 4; kc++) {
        const int kb = kc * 8;
        unsigned a0[2][4], a1[2][4];
#pragma unroll
        for (int mb = 0; mb < 2; mb++) {
            const int r0 = rbase + mb * 16 + gid;
            a0[mb][0] = Ab[0][r0][kb + tig];
            a0[mb][1] = Ab[0][r0 + 8][kb + tig];
            a0[mb][2] = Ab[0][r0][kb + tig + 4];
            a0[mb][3] = Ab[0][r0 + 8][kb + tig + 4];
            a1[mb][0] = Ab[1][r0][kb + tig];
            a1[mb][1] = Ab[1][r0 + 8][kb + tig];
            a1[mb][2] = Ab[1][r0][kb + tig + 4];
            a1[mb][3] = Ab[1][r0 + 8][kb + tig + 4];
        }
#pragma unroll
        for (int nt = 0; nt < 4; nt++) {
            int n = cbase + nt * 8 + gid;
            unsigned b00 = Bb[0][n][kb + tig];
            unsigned b01 = Bb[0][n][kb + tig + 4];
            unsigned b10 = Bb[1][n][kb + tig];
            unsigned b11 = Bb[1][n][kb + tig + 4];
#pragma unroll
            for (int mb = 0; mb < 2; mb++) {
                mma_bf16(acc[mb][nt], a0[mb][0], a0[mb][1], a0[mb][2], a0[mb][3], b00, b01);
                mma_bf16(acc[mb][nt], a0[mb][0], a0[mb][1], a0[mb][2], a0[mb][3], b10, b11);
                mma_bf16(acc[mb][nt], a1[mb][0], a1[mb][1], a1[mb][2], a1[mb][3], b00, b01);
            }
        }
    }

#pragma unroll
    for (int mb = 0; mb < 2; mb++)
#pragma unroll
        for (int nt = 0; nt < 4; nt++) {
            int c = cbase + nt * 8 + 2 * tig;
            float bb0 = 0.f, bb1 = 0.f;
            if (BIAS) { bb0 = bias[bn + c]; bb1 = bias[bn + c + 1]; }
#pragma unroll
            for (int half = 0; half < 2; half++) {
                int gr = bm + rbase + mb * 16 + gid + half * 8;
                if (gr >= M) continue;
                float v0 = acc[mb][nt][half * 2 + 0] + bb0;
                float v1 = acc[mb][nt][half * 2 + 1] + bb1;
                if (RELU) { v0 = fmaxf(v0, 0.0f); v1 = fmaxf(v1, 0.0f); }
                *reinterpret_cast<float2*>(&Csel[(size_t)gr * NcC + bn + c]) = make_float2(v0, v1);
            }
        }
}

// ---------------- fused GAT: softmax + aggregate + head-mean, warp per dst ---
// Lane l owns relation-slice channels 8l..8l+7 (head = l>>3).
// For each relation: keep fd row in regs, stream incoming edges from CSR,
// dot -> exp -> accumulate numerator + denominator in one pass. No atomics.
__global__ void gat_fused(const float* __restrict__ fs,
                          const float* __restrict__ fd,
                          const int* __restrict__ rowptr,
                          const int* __restrict__ rowend,
                          const int* __restrict__ csr,
                          float* __restrict__ hmean) {
    int w = (blockIdx.x * blockDim.x + threadIdx.x) >> 5;
    if (w >= NN) return;
    int lane = threadIdx.x & 31;
    float out[8];
#pragma unroll
    for (int j = 0; j < 8; j++) out[j] = 0.f;

#pragma unroll
    for (int r = 0; r < 3; r++) {
        const float4* pfd = reinterpret_cast<const float4*>(
            fd + (size_t)w * FDR + r * 256 + 8 * lane);
        float4 d0 = pfd[0], d1 = pfd[1];
        float accv[8];
#pragma unroll
        for (int j = 0; j < 8; j++) accv[j] = 0.f;
        float dn = 0.f;
        int idx = r * NN + w;
        int beg = rowptr[idx];
        int end = rowend[idx];      // cursor after scatter == row end
        for (int i = beg; i < end; i++) {
            int s = csr[i];
            const float4* pfs = reinterpret_cast<const float4*>(
                fs + (size_t)s * FDR + r * 256 + 8 * lane);
            float4 f0 = pfs[0], f1 = pfs[1];
            float dot = f0.x * d0.x + f0.y * d0.y + f0.z * d0.z + f0.w * d0.w +
                        f1.x * d1.x + f1.y * d1.y + f1.z * d1.z + f1.w * d1.w;
            dot += __shfl_xor_sync(0xffffffffu, dot, 4);
            dot += __shfl_xor_sync(0xffffffffu, dot, 2);
            dot += __shfl_xor_sync(0xffffffffu, dot, 1);
            float p = expf(dot * SCALEF);
            dn += p;
            accv[0] += p * f0.x; accv[1] += p * f0.y;
            accv[2] += p * f0.z; accv[3] += p * f0.w;
            accv[4] += p * f1.x; accv[5] += p * f1.y;
            accv[6] += p * f1.z; accv[7] += p * f1.w;
        }
        float inv = 0.25f / fmaxf(dn, 1e-9f);
#pragma unroll
        for (int j = 0; j < 8; j++) out[j] += accv[j] * inv;
    }
    // head-mean: sum lanes {l, l+8, l+16, l+24} (4 heads, same channel set)
#pragma unroll
    for (int j = 0; j < 8; j++) {
        out[j] += __shfl_xor_sync(0xffffffffu, out[j], 8);
        out[j] += __shfl_xor_sync(0xffffffffu, out[j], 16);
    }
    if (lane < 8) {
        float4* ph = reinterpret_cast<float4*>(hmean + (size_t)w * HD + 8 * lane);
        ph[0] = make_float4(out[0], out[1], out[2], out[3]);
        ph[1] = make_float4(out[4], out[5], out[6], out[7]);
    }
}

// ---------------- batchnorm --------------------------------------------------
__global__ void bn_stats_kernel(const float* __restrict__ x,
                                float* __restrict__ bnstat) {
    int ch = threadIdx.x & 63;
    int rr = threadIdx.x >> 6;
    float s = 0.0f, s2 = 0.0f;
    for (int n = blockIdx.x * 4 + rr; n < NN; n += gridDim.x * 4) {
        float v = x[n * HD + ch];
        s += v; s2 += v * v;
    }
    __shared__ float sh[256], sh2[256];
    sh[threadIdx.x] = s; sh2[threadIdx.x] = s2;
    __syncthreads();
    if (rr == 0) {
        s  = sh[ch] + sh[64 + ch] + sh[128 + ch] + sh[192 + ch];
        s2 = sh2[ch] + sh2[64 + ch] + sh2[128 + ch] + sh2[192 + ch];
        atomicAdd(&bnstat[ch], s);
        atomicAdd(&bnstat[64 + ch], s2);
    }
}

__global__ void bn_norm_kernel(float* __restrict__ x,
                               const float* __restrict__ bnstat,
                               const float* __restrict__ gamma,
                               const float* __restrict__ beta) {
    int idx = blockIdx.x * blockDim.x + threadIdx.x;
    if (idx >= NN * HD) return;
    int ch = idx & 63;
    float mu = bnstat[ch] * (1.0f / NN);
    float var = bnstat[64 + ch] * (1.0f / NN) - mu * mu;
    float inv = rsqrtf(var + EPS_BN);
    x[idx] = gamma[ch] * (x[idx] - mu) * inv + beta[ch];
}

// ---------------- host orchestration -----------------------------------------
extern "C" void kernel_launch(void* const* d_in, const int* in_sizes, int n_in,
                              void* d_out, int out_size) {
    const float* x    = (const float*)d_in[0];
    const int* src0 = (const int*)d_in[1];
    const int* dst0 = (const int*)d_in[2];
    const int* src1 = (const int*)d_in[3];
    const int* dst1 = (const int*)d_in[4];
    const int* src2 = (const int*)d_in[5];
    const int* dst2 = (const int*)d_in[6];
    const float* Wsrc = (const float*)d_in[7];
    const float* Wdst = (const float*)d_in[8];
    const float* Wfc  = (const float*)d_in[9];
    const float* bfc  = (const float*)d_in[10];
    const float* gamma= (const float*)d_in[11];
    const float* beta = (const float*)d_in[12];
    const float* Wdim = (const float*)d_in[13];
    const float* bdim = (const float*)d_in[14];
    float* out = (float*)d_out;

    float *fs, *fd, *hmean, *h, *bnstat;
    int *cnt, *rowptr, *cursor, *bsum, *csr;
    cudaGetSymbolAddress((void**)&fs,    g_fs);
    cudaGetSymbolAddress((void**)&fd,    g_fd);
    cudaGetSymbolAddress((void**)&hmean, g_hmean);
    cudaGetSymbolAddress((void**)&h,     g_h);
    cudaGetSymbolAddress((void**)&bnstat,g_bnstat);
    cudaGetSymbolAddress((void**)&cnt,   g_cnt);
    cudaGetSymbolAddress((void**)&rowptr,g_rowptr);
    cudaGetSymbolAddress((void**)&cursor,g_cursor);
    cudaGetSymbolAddress((void**)&bsum,  g_bsum);
    cudaGetSymbolAddress((void**)&csr,   g_csr);

    const int mtiles = (NN + 63) / 64;              // 782
    const dim3 grid_proj(24, mtiles);
    const dim3 grid_fc(1, mtiles);
    const dim3 grid_out(4, mtiles);
    const int nhd_blocks = (NN * HD + 255) / 256;
    const int e3_blocks = (3 * EE + 255) / 256;
    const int seg_blocks = (NSEG + 1023) / 1024;    // 147
    const int gat_blocks = (NN * 32 + 255) / 256;   // warp per dst

    // ---- build dst-CSR once (shared by both layers) ----
    filli_kernel<<<256, 256>>>(cnt, NSEG, 0);
    hist_kernel<<<e3_blocks, 256>>>(dst0, dst1, dst2, cnt);
    scan_block<<<seg_blocks, 1024>>>(cnt, rowptr, bsum, NSEG);
    scan_top<<<1, 32>>>(bsum, seg_blocks);
    add_off<<<seg_blocks, 1024>>>(rowptr, bsum, NSEG);
    copy_kernel<<<seg_blocks, 1024>>>(rowptr, cursor, NSEG);
    scatter_kernel<<<e3_blocks, 256>>>(src0, dst0, src1, dst1, src2, dst2, cursor, csr);
    // after scatter: cursor[idx] == row end

    const float* hin = x;
    for (int l = 0; l < 2; l++) {
        const float* Ws = Wsrc + (size_t)l * 3 * 64 * 256;
        const float* Wd = Wdst + (size_t)l * 3 * 64 * 256;
        gemm_bf16x3<1, 0, 0><<<grid_proj, 128>>>(hin, Ws, Wd, nullptr, fs, fd, NN, FDR, 256);
        gat_fused<<<gat_blocks, 256>>>(fs, fd, rowptr, cursor, csr, hmean);
        gemm_bf16x3<0, 1, 1><<<grid_fc, 128>>>(hmean, Wfc + (size_t)l * 64 * 64, nullptr,
                                               bfc + l * 64, h, nullptr, NN, HD, 64);
        fill_kernel<<<1, 128>>>(bnstat, 2 * HD, 0.0f);
        bn_stats_kernel<<<512, 256>>>(h, bnstat);
        bn_norm_kernel<<<nhd_blocks, 256>>>(h, bnstat, gamma + l * 64, beta + l * 64);
        hin = h;
    }
    gemm_bf16x3<0, 1, 0><<<grid_out, 128>>>(h, Wdim, nullptr, bdim, out, nullptr, NN, IND, 256);
    (void)in_sizes; (void)n_in; (void)out_size;
}

// round 12
// speedup vs baseline: 1.6679x; 1.1242x over previous
#include <cuda_runtime.h>
#include <cuda_bf16.h>
#include <cuda_fp16.h>
#include <math.h>

#define NN 50000
#define EE 250000
#define HD 64
#define NH 4
#define FDR 768         // 3 relations * 4 heads * 64
#define IND 256
#define SCALEF 0.125f   // 1/sqrt(64)
#define EPS_BN 1e-5f
#define PLD 36          // plane row stride in words (conflict-free: 4*gid+tig)
#define NSEG (3 * NN)   // CSR segments

// ---------------- scratch (static device globals; no allocation) -------------
__device__ __half g_fs[(size_t)NN * FDR];
__device__ __half g_fd[(size_t)NN * FDR];
__device__ float g_hmean[NN * HD];
__device__ float g_h[NN * HD];
__device__ float g_bnstat[2 * HD];
__device__ int   g_cnt[NSEG];
__device__ int   g_rowptr[NSEG];
__device__ int   g_cursor[NSEG];
__device__ int   g_bsum[256];
__device__ int   g_csr[3 * EE];

// ---------------- fills -------------------------------------------------------
__global__ void fill_kernel(float* __restrict__ p, int n, float v) {
    int i = blockIdx.x * blockDim.x + threadIdx.x;
    int stride = gridDim.x * blockDim.x;
    for (; i < n; i += stride) p[i] = v;
}
__global__ void filli_kernel(int* __restrict__ p, int n, int v) {
    int i = blockIdx.x * blockDim.x + threadIdx.x;
    int stride = gridDim.x * blockDim.x;
    for (; i < n; i += stride) p[i] = v;
}

// ---------------- CSR build ---------------------------------------------------
__global__ void hist_kernel(const int* __restrict__ d0, const int* __restrict__ d1,
                            const int* __restrict__ d2, int* __restrict__ cnt) {
    int i = blockIdx.x * blockDim.x + threadIdx.x;
    if (i >= 3 * EE) return;
    int r = i / EE, e = i - r * EE;
    const int* dp = (r == 0) ? d0 : (r == 1) ? d1 : d2;
    atomicAdd(&cnt[r * NN + dp[e]], 1);
}

__global__ void scan_block(const int* __restrict__ in, int* __restrict__ out,
                           int* __restrict__ bsum, int n) {
    __shared__ int sh[1024];
    int gid = blockIdx.x * 1024 + threadIdx.x;
    int v = (gid < n) ? in[gid] : 0;
    sh[threadIdx.x] = v;
    __syncthreads();
    for (int off = 1; off < 1024; off <<= 1) {
        int t = (threadIdx.x >= off) ? sh[threadIdx.x - off] : 0;
        __syncthreads();
        sh[threadIdx.x] += t;
        __syncthreads();
    }
    if (gid < n) out[gid] = sh[threadIdx.x] - v;   // exclusive
    if (threadIdx.x == 1023) bsum[blockIdx.x] = sh[1023];
}

__global__ void scan_bsum(int* __restrict__ bsum, int nb) {
    __shared__ int sh[256];
    int v = (threadIdx.x < nb) ? bsum[threadIdx.x] : 0;
    sh[threadIdx.x] = v;
    __syncthreads();
    for (int off = 1; off < 256; off <<= 1) {
        int t = (threadIdx.x >= off) ? sh[threadIdx.x - off] : 0;
        __syncthreads();
        sh[threadIdx.x] += t;
        __syncthreads();
    }
    if (threadIdx.x < nb) bsum[threadIdx.x] = sh[threadIdx.x] - v;  // exclusive
}

__global__ void add_off(int* __restrict__ rowptr, int* __restrict__ cursor,
                        const int* __restrict__ bsum, int n) {
    int gid = blockIdx.x * 1024 + threadIdx.x;
    if (gid < n) {
        int v = rowptr[gid] + bsum[blockIdx.x];
        rowptr[gid] = v;
        cursor[gid] = v;
    }
}

__global__ void scatter_kernel(const int* __restrict__ s0, const int* __restrict__ d0,
                               const int* __restrict__ s1, const int* __restrict__ d1,
                               const int* __restrict__ s2, const int* __restrict__ d2,
                               int* __restrict__ cursor, int* __restrict__ csr) {
    int i = blockIdx.x * blockDim.x + threadIdx.x;
    if (i >= 3 * EE) return;
    int r = i / EE, e = i - r * EE;
    const int* sp = (r == 0) ? s0 : (r == 1) ? s1 : s2;
    const int* dp = (r == 0) ? d0 : (r == 1) ? d1 : d2;
    int pos = atomicAdd(&cursor[r * NN + dp[e]], 1);
    csr[pos] = sp[e];
}

// ---------------- bf16 split helpers -----------------------------------------
__device__ __forceinline__ void bsplit(float x, unsigned short& b0, unsigned short& b1) {
    __nv_bfloat16 h0 = __float2bfloat16(x);
    b0 = __bfloat16_as_ushort(h0);
    b1 = __bfloat16_as_ushort(__float2bfloat16(x - __bfloat162float(h0)));
}
__device__ __forceinline__ unsigned pack2(unsigned short lo, unsigned short hi) {
    return (unsigned)lo | ((unsigned)hi << 16);
}
__device__ __forceinline__ void mma_bf16(float* c,
                                         unsigned a0, unsigned a1, unsigned a2, unsigned a3,
                                         unsigned b0, unsigned b1) {
    asm volatile("mma.sync.aligned.m16n8k16.row.col.f32.bf16.bf16.f32 "
                 "{%0,%1,%2,%3}, {%4,%5,%6,%7}, {%8,%9}, {%0,%1,%2,%3};"
                 : "+f"(c[0]), "+f"(c[1]), "+f"(c[2]), "+f"(c[3])
                 : "r"(a0), "r"(a1), "r"(a2), "r"(a3), "r"(b0), "r"(b1));
}

// ---------------- GEMM: 64x64 tile, 4 warps of 32x32, bf16x3 -----------------
// DUAL=1: cols [0,768)->Bsrc/Cs, [768,1536)->Bdst/Cd. HOUT=1: emit __half2.
template <int DUAL, int BIAS, int RELU, int HOUT>
__global__ void gemm_bf16x3(const float* __restrict__ A,
                            const float* __restrict__ Bsrc,
                            const float* __restrict__ Bdst,
                            const float* __restrict__ bias,
                            void* __restrict__ Cs,
                            void* __restrict__ Cd,
                            int M, int NcC, int ldb) {
    __shared__ unsigned Ab[2][64][PLD];
    __shared__ unsigned Bb[2][64][PLD];

    const int bm = blockIdx.y * 64;
    int bn = blockIdx.x * 64;
    const int tid = threadIdx.x;

    const float* Bsel = Bsrc;
    void* Csel = Cs;
    if (DUAL && bn >= 768) { Bsel = Bdst; Csel = Cd; bn -= 768; }
    const float* Bblk = Bsel + (size_t)(bn >> 8) * (64 * 256) + (bn & 255);

    for (int i = tid; i < 64 * 16; i += 128) {
        int r = i >> 4, q = i & 15;
        int gr = bm + r;
        float4 v = make_float4(0.f, 0.f, 0.f, 0.f);
        if (gr < M) v = *reinterpret_cast<const float4*>(&A[(size_t)gr * 64 + 4 * q]);
        unsigned short x0, x1, y0, y1, z0, z1, w0, w1;
        bsplit(v.x, x0, x1); bsplit(v.y, y0, y1);
        bsplit(v.z, z0, z1); bsplit(v.w, w0, w1);
        Ab[0][r][2 * q]     = pack2(x0, y0);
        Ab[0][r][2 * q + 1] = pack2(z0, w0);
        Ab[1][r][2 * q]     = pack2(x1, y1);
        Ab[1][r][2 * q + 1] = pack2(z1, w1);
    }
    for (int i = tid; i < 32 * 16; i += 128) {
        int j = i >> 4, q = i & 15;
        float4 v0 = *reinterpret_cast<const float4*>(&Bblk[(size_t)(2 * j) * ldb + 4 * q]);
        float4 v1 = *reinterpret_cast<const float4*>(&Bblk[(size_t)(2 * j + 1) * ldb + 4 * q]);
        const float e0[4] = {v0.x, v0.y, v0.z, v0.w};
        const float e1[4] = {v1.x, v1.y, v1.z, v1.w};
#pragma unroll
        for (int c = 0; c < 4; c++) {
            unsigned short p0, p1, q0, q1;
            bsplit(e0[c], p0, p1);
            bsplit(e1[c], q0, q1);
            Bb[0][4 * q + c][j] = pack2(p0, q0);
            Bb[1][4 * q + c][j] = pack2(p1, q1);
        }
    }
    __syncthreads();

    const int warp = tid >> 5, lane = tid & 31;
    const int rowg = warp >> 1, colg = warp & 1;
    const int rbase = rowg * 32, cbase = colg * 32;
    const int gid = lane >> 2, tig = lane & 3;

    float acc[2][4][4];
#pragma unroll
    for (int mb = 0; mb < 2; mb++)
#pragma unroll
        for (int nt = 0; nt < 4; nt++)
#pragma unroll
            for (int j = 0; j < 4; j++) acc[mb][nt][j] = 0.0f;

#pragma unroll
    for (int kc = 0; kc < 4; kc++) {
        const int kb = kc * 8;
        unsigned a0[2][4], a1[2][4];
#pragma unroll
        for (int mb = 0; mb < 2; mb++) {
            const int r0 = rbase + mb * 16 + gid;
            a0[mb][0] = Ab[0][r0][kb + tig];
            a0[mb][1] = Ab[0][r0 + 8][kb + tig];
            a0[mb][2] = Ab[0][r0][kb + tig + 4];
            a0[mb][3] = Ab[0][r0 + 8][kb + tig + 4];
            a1[mb][0] = Ab[1][r0][kb + tig];
            a1[mb][1] = Ab[1][r0 + 8][kb + tig];
            a1[mb][2] = Ab[1][r0][kb + tig + 4];
            a1[mb][3] = Ab[1][r0 + 8][kb + tig + 4];
        }
#pragma unroll
        for (int nt = 0; nt < 4; nt++) {
            int n = cbase + nt * 8 + gid;
            unsigned b00 = Bb[0][n][kb + tig];
            unsigned b01 = Bb[0][n][kb + tig + 4];
            unsigned b10 = Bb[1][n][kb + tig];
            unsigned b11 = Bb[1][n][kb + tig + 4];
#pragma unroll
            for (int mb = 0; mb < 2; mb++) {
                mma_bf16(acc[mb][nt], a0[mb][0], a0[mb][1], a0[mb][2], a0[mb][3], b00, b01);
                mma_bf16(acc[mb][nt], a0[mb][0], a0[mb][1], a0[mb][2], a0[mb][3], b10, b11);
                mma_bf16(acc[mb][nt], a1[mb][0], a1[mb][1], a1[mb][2], a1[mb][3], b00, b01);
            }
        }
    }

#pragma unroll
    for (int mb = 0; mb < 2; mb++)
#pragma unroll
        for (int nt = 0; nt < 4; nt++) {
            int c = cbase + nt * 8 + 2 * tig;
            float bb0 = 0.f, bb1 = 0.f;
            if (BIAS) { bb0 = bias[bn + c]; bb1 = bias[bn + c + 1]; }
#pragma unroll
            for (int half = 0; half < 2; half++) {
                int gr = bm + rbase + mb * 16 + gid + half * 8;
                if (gr >= M) continue;
                float v0 = acc[mb][nt][half * 2 + 0] + bb0;
                float v1 = acc[mb][nt][half * 2 + 1] + bb1;
                if (RELU) { v0 = fmaxf(v0, 0.0f); v1 = fmaxf(v1, 0.0f); }
                if (HOUT) {
                    __half* Ch = (__half*)Csel;
                    *reinterpret_cast<__half2*>(&Ch[(size_t)gr * NcC + bn + c]) =
                        __floats2half2_rn(v0, v1);
                } else {
                    float* Cf = (float*)Csel;
                    *reinterpret_cast<float2*>(&Cf[(size_t)gr * NcC + bn + c]) =
                        make_float2(v0, v1);
                }
            }
        }
}

// ---------------- fp16 row load: 8 halves -> 4 float2 ------------------------
__device__ __forceinline__ void ld8h(const __half* p, float2& a, float2& b,
                                     float2& c, float2& d) {
    uint4 rv = *reinterpret_cast<const uint4*>(p);
    a = __half22float2(*reinterpret_cast<__half2*>(&rv.x));
    b = __half22float2(*reinterpret_cast<__half2*>(&rv.y));
    c = __half22float2(*reinterpret_cast<__half2*>(&rv.z));
    d = __half22float2(*reinterpret_cast<__half2*>(&rv.w));
}

// ---------------- fused GAT: softmax + aggregate + head-mean, warp per dst ---
__global__ void gat_fused(const __half* __restrict__ fs,
                          const __half* __restrict__ fd,
                          const int* __restrict__ rowptr,
                          const int* __restrict__ rowend,
                          const int* __restrict__ csr,
                          float* __restrict__ hmean) {
    int w = (blockIdx.x * blockDim.x + threadIdx.x) >> 5;
    if (w >= NN) return;
    int lane = threadIdx.x & 31;
    float out[8];
#pragma unroll
    for (int j = 0; j < 8; j++) out[j] = 0.f;

#pragma unroll
    for (int r = 0; r < 3; r++) {
        float2 d0, d1, d2, d3;
        ld8h(fd + (size_t)w * FDR + r * 256 + 8 * lane, d0, d1, d2, d3);
        float accv[8];
#pragma unroll
        for (int j = 0; j < 8; j++) accv[j] = 0.f;
        float dn = 0.f;
        int idx = r * NN + w;
        int beg = rowptr[idx];
        int end = rowend[idx];
        int s_next = (beg < end) ? csr[beg] : 0;
        for (int i = beg; i < end; i++) {
            int s = s_next;
            if (i + 1 < end) s_next = csr[i + 1];
            float2 f0, f1, f2, f3;
            ld8h(fs + (size_t)s * FDR + r * 256 + 8 * lane, f0, f1, f2, f3);
            float dot = f0.x * d0.x + f0.y * d0.y + f1.x * d1.x + f1.y * d1.y +
                        f2.x * d2.x + f2.y * d2.y + f3.x * d3.x + f3.y * d3.y;
            dot += __shfl_xor_sync(0xffffffffu, dot, 4);
            dot += __shfl_xor_sync(0xffffffffu, dot, 2);
            dot += __shfl_xor_sync(0xffffffffu, dot, 1);
            float p = __expf(dot * SCALEF);
            dn += p;
            accv[0] += p * f0.x; accv[1] += p * f0.y;
            accv[2] += p * f1.x; accv[3] += p * f1.y;
            accv[4] += p * f2.x; accv[5] += p * f2.y;
            accv[6] += p * f3.x; accv[7] += p * f3.y;
        }
        float inv = 0.25f / fmaxf(dn, 1e-9f);
#pragma unroll
        for (int j = 0; j < 8; j++) out[j] += accv[j] * inv;
    }
    // head-mean: sum lanes {l, l+8, l+16, l+24}
#pragma unroll
    for (int j = 0; j < 8; j++) {
        out[j] += __shfl_xor_sync(0xffffffffu, out[j], 8);
        out[j] += __shfl_xor_sync(0xffffffffu, out[j], 16);
    }
    if (lane < 8) {
        float4* ph = reinterpret_cast<float4*>(hmean + (size_t)w * HD + 8 * lane);
        ph[0] = make_float4(out[0], out[1], out[2], out[3]);
        ph[1] = make_float4(out[4], out[5], out[6], out[7]);
    }
}

// ---------------- batchnorm --------------------------------------------------
__global__ void bn_stats_kernel(const float* __restrict__ x,
                                float* __restrict__ bnstat) {
    int ch = threadIdx.x & 63;
    int rr = threadIdx.x >> 6;
    float s = 0.0f, s2 = 0.0f;
    for (int n = blockIdx.x * 4 + rr; n < NN; n += gridDim.x * 4) {
        float v = x[n * HD + ch];
        s += v; s2 += v * v;
    }
    __shared__ float sh[256], sh2[256];
    sh[threadIdx.x] = s; sh2[threadIdx.x] = s2;
    __syncthreads();
    if (rr == 0) {
        s  = sh[ch] + sh[64 + ch] + sh[128 + ch] + sh[192 + ch];
        s2 = sh2[ch] + sh2[64 + ch] + sh2[128 + ch] + sh2[192 + ch];
        atomicAdd(&bnstat[ch], s);
        atomicAdd(&bnstat[64 + ch], s2);
    }
}

__global__ void bn_norm_kernel(float* __restrict__ x,
                               const float* __restrict__ bnstat,
                               const float* __restrict__ gamma,
                               const float* __restrict__ beta) {
    int idx = blockIdx.x * blockDim.x + threadIdx.x;
    if (idx >= NN * HD) return;
    int ch = idx & 63;
    float mu = bnstat[ch] * (1.0f / NN);
    float var = bnstat[64 + ch] * (1.0f / NN) - mu * mu;
    float inv = rsqrtf(var + EPS_BN);
    x[idx] = gamma[ch] * (x[idx] - mu) * inv + beta[ch];
}

// ---------------- host orchestration -----------------------------------------
extern "C" void kernel_launch(void* const* d_in, const int* in_sizes, int n_in,
                              void* d_out, int out_size) {
    const float* x    = (const float*)d_in[0];
    const int* src0 = (const int*)d_in[1];
    const int* dst0 = (const int*)d_in[2];
    const int* src1 = (const int*)d_in[3];
    const int* dst1 = (const int*)d_in[4];
    const int* src2 = (const int*)d_in[5];
    const int* dst2 = (const int*)d_in[6];
    const float* Wsrc = (const float*)d_in[7];
    const float* Wdst = (const float*)d_in[8];
    const float* Wfc  = (const float*)d_in[9];
    const float* bfc  = (const float*)d_in[10];
    const float* gamma= (const float*)d_in[11];
    const float* beta = (const float*)d_in[12];
    const float* Wdim = (const float*)d_in[13];
    const float* bdim = (const float*)d_in[14];
    float* out = (float*)d_out;

    __half *fs, *fd;
    float *hmean, *h, *bnstat;
    int *cnt, *rowptr, *cursor, *bsum, *csr;
    cudaGetSymbolAddress((void**)&fs,    g_fs);
    cudaGetSymbolAddress((void**)&fd,    g_fd);
    cudaGetSymbolAddress((void**)&hmean, g_hmean);
    cudaGetSymbolAddress((void**)&h,     g_h);
    cudaGetSymbolAddress((void**)&bnstat,g_bnstat);
    cudaGetSymbolAddress((void**)&cnt,   g_cnt);
    cudaGetSymbolAddress((void**)&rowptr,g_rowptr);
    cudaGetSymbolAddress((void**)&cursor,g_cursor);
    cudaGetSymbolAddress((void**)&bsum,  g_bsum);
    cudaGetSymbolAddress((void**)&csr,   g_csr);

    const int mtiles = (NN + 63) / 64;              // 782
    const dim3 grid_proj(24, mtiles);
    const dim3 grid_fc(1, mtiles);
    const dim3 grid_out(4, mtiles);
    const int nhd_blocks = (NN * HD + 255) / 256;
    const int e3_blocks = (3 * EE + 255) / 256;
    const int seg_blocks = (NSEG + 1023) / 1024;    // 147
    const int gat_blocks = (NN * 32 + 255) / 256;   // warp per dst

    // ---- build dst-CSR once (shared by both layers) ----
    filli_kernel<<<256, 256>>>(cnt, NSEG, 0);
    hist_kernel<<<e3_blocks, 256>>>(dst0, dst1, dst2, cnt);
    scan_block<<<seg_blocks, 1024>>>(cnt, rowptr, bsum, NSEG);
    scan_bsum<<<1, 256>>>(bsum, seg_blocks);
    add_off<<<seg_blocks, 1024>>>(rowptr, cursor, bsum, NSEG);
    scatter_kernel<<<e3_blocks, 256>>>(src0, dst0, src1, dst1, src2, dst2, cursor, csr);
    // after scatter: cursor[idx] == row end

    const float* hin = x;
    for (int l = 0; l < 2; l++) {
        const float* Ws = Wsrc + (size_t)l * 3 * 64 * 256;
        const float* Wd = Wdst + (size_t)l * 3 * 64 * 256;
        gemm_bf16x3<1, 0, 0, 1><<<grid_proj, 128>>>(hin, Ws, Wd, nullptr, fs, fd, NN, FDR, 256);
        gat_fused<<<gat_blocks, 256>>>(fs, fd, rowptr, cursor, csr, hmean);
        gemm_bf16x3<0, 1, 1, 0><<<grid_fc, 128>>>(hmean, Wfc + (size_t)l * 64 * 64, nullptr,
                                                  bfc + l * 64, h, nullptr, NN, HD, 64);
        fill_kernel<<<1, 128>>>(bnstat, 2 * HD, 0.0f);
        bn_stats_kernel<<<512, 256>>>(h, bnstat);
        bn_norm_kernel<<<nhd_blocks, 256>>>(h, bnstat, gamma + l * 64, beta + l * 64);
        hin = h;
    }
    gemm_bf16x3<0, 1, 0, 0><<<grid_out, 128>>>(h, Wdim, nullptr, bdim, out, nullptr, NN, IND, 256);
    (void)in_sizes; (void)n_in; (void)out_size;
}

// round 16
// speedup vs baseline: 1.8479x; 1.1079x over previous
#include <cuda_runtime.h>
#include <cuda_bf16.h>
#include <cuda_fp16.h>
#include <math.h>

#define NN 50000
#define EE 250000
#define HD 64
#define NH 4
#define FDR 768         // 3 relations * 4 heads * 64
#define IND 256
#define SCALEF 0.125f   // 1/sqrt(64)
#define EPS_BN 1e-5f
#define PLD 36          // plane row stride (words), conflict-free (4*gid+tig)
#define NSEG (3 * NN)   // CSR segments

// ---------------- scratch (static device globals; no allocation) -------------
__device__ __half g_fs[(size_t)NN * FDR];
__device__ __half g_fd[(size_t)NN * FDR];
__device__ float g_hmean[NN * HD];
__device__ float g_h[NN * HD];
__device__ float g_bnstat[2 * HD];
__device__ int   g_cnt[NSEG];
__device__ int   g_rowptr[NSEG];
__device__ int   g_cursor[NSEG];
__device__ int   g_bsum[256];
__device__ int   g_csr[3 * EE];

// ---------------- fills -------------------------------------------------------
__global__ void fill_kernel(float* __restrict__ p, int n, float v) {
    int i = blockIdx.x * blockDim.x + threadIdx.x;
    int stride = gridDim.x * blockDim.x;
    for (; i < n; i += stride) p[i] = v;
}
__global__ void filli_kernel(int* __restrict__ p, int n, int v) {
    int i = blockIdx.x * blockDim.x + threadIdx.x;
    int stride = gridDim.x * blockDim.x;
    for (; i < n; i += stride) p[i] = v;
}

// ---------------- CSR build ---------------------------------------------------
__global__ void hist_kernel(const int* __restrict__ d0, const int* __restrict__ d1,
                            const int* __restrict__ d2, int* __restrict__ cnt) {
    int i = blockIdx.x * blockDim.x + threadIdx.x;
    if (i >= 3 * EE) return;
    int r = i / EE, e = i - r * EE;
    const int* dp = (r == 0) ? d0 : (r == 1) ? d1 : d2;
    atomicAdd(&cnt[r * NN + dp[e]], 1);
}

__global__ void scan_block(const int* __restrict__ in, int* __restrict__ out,
                           int* __restrict__ bsum, int n) {
    __shared__ int sh[1024];
    int gid = blockIdx.x * 1024 + threadIdx.x;
    int v = (gid < n) ? in[gid] : 0;
    sh[threadIdx.x] = v;
    __syncthreads();
    for (int off = 1; off < 1024; off <<= 1) {
        int t = (threadIdx.x >= off) ? sh[threadIdx.x - off] : 0;
        __syncthreads();
        sh[threadIdx.x] += t;
        __syncthreads();
    }
    if (gid < n) out[gid] = sh[threadIdx.x] - v;   // exclusive
    if (threadIdx.x == 1023) bsum[blockIdx.x] = sh[1023];
}

__global__ void scan_bsum(int* __restrict__ bsum, int nb) {
    __shared__ int sh[256];
    int v = (threadIdx.x < nb) ? bsum[threadIdx.x] : 0;
    sh[threadIdx.x] = v;
    __syncthreads();
    for (int off = 1; off < 256; off <<= 1) {
        int t = (threadIdx.x >= off) ? sh[threadIdx.x - off] : 0;
        __syncthreads();
        sh[threadIdx.x] += t;
        __syncthreads();
    }
    if (threadIdx.x < nb) bsum[threadIdx.x] = sh[threadIdx.x] - v;  // exclusive
}

__global__ void add_off(int* __restrict__ rowptr, int* __restrict__ cursor,
                        const int* __restrict__ bsum, int n) {
    int gid = blockIdx.x * 1024 + threadIdx.x;
    if (gid < n) {
        int v = rowptr[gid] + bsum[blockIdx.x];
        rowptr[gid] = v;
        cursor[gid] = v;
    }
}

__global__ void scatter_kernel(const int* __restrict__ s0, const int* __restrict__ d0,
                               const int* __restrict__ s1, const int* __restrict__ d1,
                               const int* __restrict__ s2, const int* __restrict__ d2,
                               int* __restrict__ cursor, int* __restrict__ csr) {
    int i = blockIdx.x * blockDim.x + threadIdx.x;
    if (i >= 3 * EE) return;
    int r = i / EE, e = i - r * EE;
    const int* sp = (r == 0) ? s0 : (r == 1) ? s1 : s2;
    const int* dp = (r == 0) ? d0 : (r == 1) ? d1 : d2;
    int pos = atomicAdd(&cursor[r * NN + dp[e]], 1);
    csr[pos] = sp[e];
}

// ---------------- split/pack helpers -----------------------------------------
__device__ __forceinline__ void bsplit(float x, unsigned short& b0, unsigned short& b1) {
    __nv_bfloat16 h0 = __float2bfloat16(x);
    b0 = __bfloat16_as_ushort(h0);
    b1 = __bfloat16_as_ushort(__float2bfloat16(x - __bfloat162float(h0)));
}
__device__ __forceinline__ unsigned pack2(unsigned short lo, unsigned short hi) {
    return (unsigned)lo | ((unsigned)hi << 16);
}
__device__ __forceinline__ unsigned packh2(float a, float b) {
    __half2 h = __floats2half2_rn(a, b);
    return *reinterpret_cast<unsigned*>(&h);
}
__device__ __forceinline__ void mma_bf16(float* c,
                                         unsigned a0, unsigned a1, unsigned a2, unsigned a3,
                                         unsigned b0, unsigned b1) {
    asm volatile("mma.sync.aligned.m16n8k16.row.col.f32.bf16.bf16.f32 "
                 "{%0,%1,%2,%3}, {%4,%5,%6,%7}, {%8,%9}, {%0,%1,%2,%3};"
                 : "+f"(c[0]), "+f"(c[1]), "+f"(c[2]), "+f"(c[3])
                 : "r"(a0), "r"(a1), "r"(a2), "r"(a3), "r"(b0), "r"(b1));
}
__device__ __forceinline__ void mma_f16(float* c,
                                        unsigned a0, unsigned a1, unsigned a2, unsigned a3,
                                        unsigned b0, unsigned b1) {
    asm volatile("mma.sync.aligned.m16n8k16.row.col.f32.f16.f16.f32 "
                 "{%0,%1,%2,%3}, {%4,%5,%6,%7}, {%8,%9}, {%0,%1,%2,%3};"
                 : "+f"(c[0]), "+f"(c[1]), "+f"(c[2]), "+f"(c[3])
                 : "r"(a0), "r"(a1), "r"(a2), "r"(a3), "r"(b0), "r"(b1));
}

// ---------------- proj GEMM: C[M,768] = A[M,64] @ B(3 rel), fp16 out ---------
// 64x64 block tile, 128 threads = 4 warps (2x2), warp tile 32x32.
// HPREC=0: bf16x3 compensated (value path, fs). HPREC=1: plain fp16 (fd logits).
template <int HPREC>
__global__ void gemm_proj(const float* __restrict__ A,
                          const float* __restrict__ B,
                          __half* __restrict__ C, int M) {
    __shared__ unsigned Ab[HPREC ? 1 : 2][64][PLD];
    __shared__ unsigned Bb[HPREC ? 1 : 2][64][PLD];

    const int bm = blockIdx.y * 64;
    const int bn = blockIdx.x * 64;
    const int tid = threadIdx.x;
    const float* Bblk = B + (size_t)(bn >> 8) * (64 * 256) + (bn & 255);

    // A tile: 64 rows x 16 k-quads
    for (int i = tid; i < 64 * 16; i += 128) {
        int r = i >> 4, q = i & 15;
        int gr = bm + r;
        float4 v = make_float4(0.f, 0.f, 0.f, 0.f);
        if (gr < M) v = *reinterpret_cast<const float4*>(&A[(size_t)gr * 64 + 4 * q]);
        if (HPREC) {
            Ab[0][r][2 * q]     = packh2(v.x, v.y);
            Ab[0][r][2 * q + 1] = packh2(v.z, v.w);
        } else {
            unsigned short x0, x1, y0, y1, z0, z1, w0, w1;
            bsplit(v.x, x0, x1); bsplit(v.y, y0, y1);
            bsplit(v.z, z0, z1); bsplit(v.w, w0, w1);
            Ab[0][r][2 * q]     = pack2(x0, y0);
            Ab[0][r][2 * q + 1] = pack2(z0, w0);
            Ab[HPREC ? 0 : 1][r][2 * q]     = pack2(x1, y1);
            Ab[HPREC ? 0 : 1][r][2 * q + 1] = pack2(z1, w1);
        }
    }
    // B tile: 32 k-pairs x 16 n-quads; transpose into [n][kpair] planes
    for (int i = tid; i < 32 * 16; i += 128) {
        int j = i >> 4, q = i & 15;
        float4 v0 = *reinterpret_cast<const float4*>(&Bblk[(size_t)(2 * j) * 256 + 4 * q]);
        float4 v1 = *reinterpret_cast<const float4*>(&Bblk[(size_t)(2 * j + 1) * 256 + 4 * q]);
        const float e0[4] = {v0.x, v0.y, v0.z, v0.w};
        const float e1[4] = {v1.x, v1.y, v1.z, v1.w};
#pragma unroll
        for (int c = 0; c < 4; c++) {
            if (HPREC) {
                Bb[0][4 * q + c][j] = packh2(e0[c], e1[c]);
            } else {
                unsigned short p0, p1, q0, q1;
                bsplit(e0[c], p0, p1);
                bsplit(e1[c], q0, q1);
                Bb[0][4 * q + c][j] = pack2(p0, q0);
                Bb[HPREC ? 0 : 1][4 * q + c][j] = pack2(p1, q1);
            }
        }
    }
    __syncthreads();

    const int warp = tid >> 5, lane = tid & 31;
    const int rowg = warp >> 1, colg = warp & 1;
    const int rbase = rowg * 32, cbase = colg * 32;
    const int gid = lane >> 2, tig = lane & 3;

    float acc[2][4][4];
#pragma unroll
    for (int mb = 0; mb < 2; mb++)
#pragma unroll
        for (int nt = 0; nt < 4; nt++)
#pragma unroll
            for (int j = 0; j < 4; j++) acc[mb][nt][j] = 0.0f;

#pragma unroll
    for (int kc = 0; kc < 4; kc++) {
        const int kb = kc * 8;
        unsigned a0[2][4], a1[2][4];
#pragma unroll
        for (int mb = 0; mb < 2; mb++) {
            const int r0 = rbase + mb * 16 + gid;
            a0[mb][0] = Ab[0][r0][kb + tig];
            a0[mb][1] = Ab[0][r0 + 8][kb + tig];
            a0[mb][2] = Ab[0][r0][kb + tig + 4];
            a0[mb][3] = Ab[0][r0 + 8][kb + tig + 4];
            if (!HPREC) {
                a1[mb][0] = Ab[1][r0][kb + tig];
                a1[mb][1] = Ab[1][r0 + 8][kb + tig];
                a1[mb][2] = Ab[1][r0][kb + tig + 4];
                a1[mb][3] = Ab[1][r0 + 8][kb + tig + 4];
            }
        }
#pragma unroll
        for (int nt = 0; nt < 4; nt++) {
            int n = cbase + nt * 8 + gid;
            unsigned b00 = Bb[0][n][kb + tig];
            unsigned b01 = Bb[0][n][kb + tig + 4];
            if (HPREC) {
#pragma unroll
                for (int mb = 0; mb < 2; mb++)
                    mma_f16(acc[mb][nt], a0[mb][0], a0[mb][1], a0[mb][2], a0[mb][3], b00, b01);
            } else {
                unsigned b10 = Bb[1][n][kb + tig];
                unsigned b11 = Bb[1][n][kb + tig + 4];
#pragma unroll
                for (int mb = 0; mb < 2; mb++) {
                    mma_bf16(acc[mb][nt], a0[mb][0], a0[mb][1], a0[mb][2], a0[mb][3], b00, b01);
                    mma_bf16(acc[mb][nt], a0[mb][0], a0[mb][1], a0[mb][2], a0[mb][3], b10, b11);
                    mma_bf16(acc[mb][nt], a1[mb][0], a1[mb][1], a1[mb][2], a1[mb][3], b00, b01);
                }
            }
        }
    }

#pragma unroll
    for (int mb = 0; mb < 2; mb++)
#pragma unroll
        for (int nt = 0; nt < 4; nt++) {
            int c = cbase + nt * 8 + 2 * tig;
#pragma unroll
            for (int half = 0; half < 2; half++) {
                int gr = bm + rbase + mb * 16 + gid + half * 8;
                if (gr >= M) continue;
                *reinterpret_cast<unsigned*>(&C[(size_t)gr * FDR + bn + c]) =
                    packh2(acc[mb][nt][half * 2 + 0], acc[mb][nt][half * 2 + 1]);
            }
        }
}

// ---------------- register-MMA GEMM (fc / out path, fp32 out) ----------------
template <int BIAS, int RELU>
__global__ void gemm_bf16x3(const float* __restrict__ A,
                            const float* __restrict__ B,
                            const float* __restrict__ bias,
                            float* __restrict__ C,
                            int M, int NcC, int ldb) {
    __shared__ unsigned Ab[2][64][PLD];
    __shared__ unsigned Bb[2][64][PLD];

    const int bm = blockIdx.y * 64;
    int bn = blockIdx.x * 64;
    const int tid = threadIdx.x;
    const float* Bblk = B + (size_t)(bn >> 8) * (64 * 256) + (bn & 255);

    for (int i = tid; i < 64 * 16; i += 128) {
        int r = i >> 4, q = i & 15;
        int gr = bm + r;
        float4 v = make_float4(0.f, 0.f, 0.f, 0.f);
        if (gr < M) v = *reinterpret_cast<const float4*>(&A[(size_t)gr * 64 + 4 * q]);
        unsigned short x0, x1, y0, y1, z0, z1, w0, w1;
        bsplit(v.x, x0, x1); bsplit(v.y, y0, y1);
        bsplit(v.z, z0, z1); bsplit(v.w, w0, w1);
        Ab[0][r][2 * q]     = pack2(x0, y0);
        Ab[0][r][2 * q + 1] = pack2(z0, w0);
        Ab[1][r][2 * q]     = pack2(x1, y1);
        Ab[1][r][2 * q + 1] = pack2(z1, w1);
    }
    for (int i = tid; i < 32 * 16; i += 128) {
        int j = i >> 4, q = i & 15;
        float4 v0 = *reinterpret_cast<const float4*>(&Bblk[(size_t)(2 * j) * ldb + 4 * q]);
        float4 v1 = *reinterpret_cast<const float4*>(&Bblk[(size_t)(2 * j + 1) * ldb + 4 * q]);
        const float e0[4] = {v0.x, v0.y, v0.z, v0.w};
        const float e1[4] = {v1.x, v1.y, v1.z, v1.w};
#pragma unroll
        for (int c = 0; c < 4; c++) {
            unsigned short p0, p1, q0, q1;
            bsplit(e0[c], p0, p1);
            bsplit(e1[c], q0, q1);
            Bb[0][4 * q + c][j] = pack2(p0, q0);
            Bb[1][4 * q + c][j] = pack2(p1, q1);
        }
    }
    __syncthreads();

    const int warp = tid >> 5, lane = tid & 31;
    const int rowg = warp >> 1, colg = warp & 1;
    const int rbase = rowg * 32, cbase = colg * 32;
    const int gid = lane >> 2, tig = lane & 3;

    float acc[2][4][4];
#pragma unroll
    for (int mb = 0; mb < 2; mb++)
#pragma unroll
        for (int nt = 0; nt < 4; nt++)
#pragma unroll
            for (int j = 0; j < 4; j++) acc[mb][nt][j] = 0.0f;

#pragma unroll
    for (int kc = 0; kc < 4; kc++) {
        const int kb = kc * 8;
        unsigned a0[2][4], a1[2][4];
#pragma unroll
        for (int mb = 0; mb < 2; mb++) {
            const int r0 = rbase + mb * 16 + gid;
            a0[mb][0] = Ab[0][r0][kb + tig];
            a0[mb][1] = Ab[0][r0 + 8][kb + tig];
            a0[mb][2] = Ab[0][r0][kb + tig + 4];
            a0[mb][3] = Ab[0][r0 + 8][kb + tig + 4];
            a1[mb][0] = Ab[1][r0][kb + tig];
            a1[mb][1] = Ab[1][r0 + 8][kb + tig];
            a1[mb][2] = Ab[1][r0][kb + tig + 4];
            a1[mb][3] = Ab[1][r0 + 8][kb + tig + 4];
        }
#pragma unroll
        for (int nt = 0; nt < 4; nt++) {
            int n = cbase + nt * 8 + gid;
            unsigned b00 = Bb[0][n][kb + tig];
            unsigned b01 = Bb[0][n][kb + tig + 4];
            unsigned b10 = Bb[1][n][kb + tig];
            unsigned b11 = Bb[1][n][kb + tig + 4];
#pragma unroll
            for (int mb = 0; mb < 2; mb++) {
                mma_bf16(acc[mb][nt], a0[mb][0], a0[mb][1], a0[mb][2], a0[mb][3], b00, b01);
                mma_bf16(acc[mb][nt], a0[mb][0], a0[mb][1], a0[mb][2], a0[mb][3], b10, b11);
                mma_bf16(acc[mb][nt], a1[mb][0], a1[mb][1], a1[mb][2], a1[mb][3], b00, b01);
            }
        }
    }

#pragma unroll
    for (int mb = 0; mb < 2; mb++)
#pragma unroll
        for (int nt = 0; nt < 4; nt++) {
            int c = cbase + nt * 8 + 2 * tig;
            float bb0 = 0.f, bb1 = 0.f;
            if (BIAS) { bb0 = bias[bn + c]; bb1 = bias[bn + c + 1]; }
#pragma unroll
            for (int half = 0; half < 2; half++) {
                int gr = bm + rbase + mb * 16 + gid + half * 8;
                if (gr >= M) continue;
                float v0 = acc[mb][nt][half * 2 + 0] + bb0;
                float v1 = acc[mb][nt][half * 2 + 1] + bb1;
                if (RELU) { v0 = fmaxf(v0, 0.0f); v1 = fmaxf(v1, 0.0f); }
                *reinterpret_cast<float2*>(&C[(size_t)gr * NcC + bn + c]) = make_float2(v0, v1);
            }
        }
}

// ---------------- fp16 row load: 8 halves -> 4 float2 ------------------------
__device__ __forceinline__ void ld8h(const __half* p, float2& a, float2& b,
                                     float2& c, float2& d) {
    uint4 rv = *reinterpret_cast<const uint4*>(p);
    a = __half22float2(*reinterpret_cast<__half2*>(&rv.x));
    b = __half22float2(*reinterpret_cast<__half2*>(&rv.y));
    c = __half22float2(*reinterpret_cast<__half2*>(&rv.z));
    d = __half22float2(*reinterpret_cast<__half2*>(&rv.w));
}

// ---------------- fused GAT: softmax + aggregate + head-mean, warp per dst ---
// Edge loop unrolled x2: two independent LDG->dot->SHFL chains interleave,
// hiding SHFL (26cyc) and gather latency.
__global__ void gat_fused(const __half* __restrict__ fs,
                          const __half* __restrict__ fd,
                          const int* __restrict__ rowptr,
                          const int* __restrict__ rowend,
                          const int* __restrict__ csr,
                          float* __restrict__ hmean) {
    int w = (blockIdx.x * blockDim.x + threadIdx.x) >> 5;
    if (w >= NN) return;
    int lane = threadIdx.x & 31;
    float out[8];
#pragma unroll
    for (int j = 0; j < 8; j++) out[j] = 0.f;

#pragma unroll
    for (int r = 0; r < 3; r++) {
        float2 d0, d1, d2, d3;
        ld8h(fd + (size_t)w * FDR + r * 256 + 8 * lane, d0, d1, d2, d3);
        float accv[8];
#pragma unroll
        for (int j = 0; j < 8; j++) accv[j] = 0.f;
        float dn = 0.f;
        int idx = r * NN + w;
        int beg = rowptr[idx];
        int end = rowend[idx];
        int i = beg;
        for (; i + 2 <= end; i += 2) {
            int s0 = csr[i], s1 = csr[i + 1];
            float2 a0, a1, a2, a3, b0, b1, b2, b3;
            ld8h(fs + (size_t)s0 * FDR + r * 256 + 8 * lane, a0, a1, a2, a3);
            ld8h(fs + (size_t)s1 * FDR + r * 256 + 8 * lane, b0, b1, b2, b3);
            float dA = a0.x * d0.x + a0.y * d0.y + a1.x * d1.x + a1.y * d1.y +
                       a2.x * d2.x + a2.y * d2.y + a3.x * d3.x + a3.y * d3.y;
            float dB = b0.x * d0.x + b0.y * d0.y + b1.x * d1.x + b1.y * d1.y +
                       b2.x * d2.x + b2.y * d2.y + b3.x * d3.x + b3.y * d3.y;
            dA += __shfl_xor_sync(0xffffffffu, dA, 4);
            dB += __shfl_xor_sync(0xffffffffu, dB, 4);
            dA += __shfl_xor_sync(0xffffffffu, dA, 2);
            dB += __shfl_xor_sync(0xffffffffu, dB, 2);
            dA += __shfl_xor_sync(0xffffffffu, dA, 1);
            dB += __shfl_xor_sync(0xffffffffu, dB, 1);
            float pA = __expf(dA * SCALEF);
            float pB = __expf(dB * SCALEF);
            dn += pA + pB;
            accv[0] += pA * a0.x + pB * b0.x; accv[1] += pA * a0.y + pB * b0.y;
            accv[2] += pA * a1.x + pB * b1.x; accv[3] += pA * a1.y + pB * b1.y;
            accv[4] += pA * a2.x + pB * b2.x; accv[5] += pA * a2.y + pB * b2.y;
            accv[6] += pA * a3.x + pB * b3.x; accv[7] += pA * a3.y + pB * b3.y;
        }
        if (i < end) {
            int s = csr[i];
            float2 f0, f1, f2, f3;
            ld8h(fs + (size_t)s * FDR + r * 256 + 8 * lane, f0, f1, f2, f3);
            float dot = f0.x * d0.x + f0.y * d0.y + f1.x * d1.x + f1.y * d1.y +
                        f2.x * d2.x + f2.y * d2.y + f3.x * d3.x + f3.y * d3.y;
            dot += __shfl_xor_sync(0xffffffffu, dot, 4);
            dot += __shfl_xor_sync(0xffffffffu, dot, 2);
            dot += __shfl_xor_sync(0xffffffffu, dot, 1);
            float p = __expf(dot * SCALEF);
            dn += p;
            accv[0] += p * f0.x; accv[1] += p * f0.y;
            accv[2] += p * f1.x; accv[3] += p * f1.y;
            accv[4] += p * f2.x; accv[5] += p * f2.y;
            accv[6] += p * f3.x; accv[7] += p * f3.y;
        }
        float inv = 0.25f / fmaxf(dn, 1e-9f);
#pragma unroll
        for (int j = 0; j < 8; j++) out[j] += accv[j] * inv;
    }
#pragma unroll
    for (int j = 0; j < 8; j++) {
        out[j] += __shfl_xor_sync(0xffffffffu, out[j], 8);
        out[j] += __shfl_xor_sync(0xffffffffu, out[j], 16);
    }
    if (lane < 8) {
        float4* ph = reinterpret_cast<float4*>(hmean + (size_t)w * HD + 8 * lane);
        ph[0] = make_float4(out[0], out[1], out[2], out[3]);
        ph[1] = make_float4(out[4], out[5], out[6], out[7]);
    }
}

// ---------------- batchnorm --------------------------------------------------
__global__ void bn_stats_kernel(const float* __restrict__ x,
                                float* __restrict__ bnstat) {
    int ch = threadIdx.x & 63;
    int rr = threadIdx.x >> 6;
    float s = 0.0f, s2 = 0.0f;
    for (int n = blockIdx.x * 4 + rr; n < NN; n += gridDim.x * 4) {
        float v = x[n * HD + ch];
        s += v; s2 += v * v;
    }
    __shared__ float sh[256], sh2[256];
    sh[threadIdx.x] = s; sh2[threadIdx.x] = s2;
    __syncthreads();
    if (rr == 0) {
        s  = sh[ch] + sh[64 + ch] + sh[128 + ch] + sh[192 + ch];
        s2 = sh2[ch] + sh2[64 + ch] + sh2[128 + ch] + sh2[192 + ch];
        atomicAdd(&bnstat[ch], s);
        atomicAdd(&bnstat[64 + ch], s2);
    }
}

__global__ void bn_norm_kernel(float* __restrict__ x,
                               const float* __restrict__ bnstat,
                               const float* __restrict__ gamma,
                               const float* __restrict__ beta) {
    int idx = blockIdx.x * blockDim.x + threadIdx.x;
    if (idx >= NN * HD) return;
    int ch = idx & 63;
    float mu = bnstat[ch] * (1.0f / NN);
    float var = bnstat[64 + ch] * (1.0f / NN) - mu * mu;
    float inv = rsqrtf(var + EPS_BN);
    x[idx] = gamma[ch] * (x[idx] - mu) * inv + beta[ch];
}

// ---------------- host orchestration -----------------------------------------
extern "C" void kernel_launch(void* const* d_in, const int* in_sizes, int n_in,
                              void* d_out, int out_size) {
    const float* x    = (const float*)d_in[0];
    const int* src0 = (const int*)d_in[1];
    const int* dst0 = (const int*)d_in[2];
    const int* src1 = (const int*)d_in[3];
    const int* dst1 = (const int*)d_in[4];
    const int* src2 = (const int*)d_in[5];
    const int* dst2 = (const int*)d_in[6];
    const float* Wsrc = (const float*)d_in[7];
    const float* Wdst = (const float*)d_in[8];
    const float* Wfc  = (const float*)d_in[9];
    const float* bfc  = (const float*)d_in[10];
    const float* gamma= (const float*)d_in[11];
    const float* beta = (const float*)d_in[12];
    const float* Wdim = (const float*)d_in[13];
    const float* bdim = (const float*)d_in[14];
    float* out = (float*)d_out;

    __half *fs, *fd;
    float *hmean, *h, *bnstat;
    int *cnt, *rowptr, *cursor, *bsum, *csr;
    cudaGetSymbolAddress((void**)&fs,    g_fs);
    cudaGetSymbolAddress((void**)&fd,    g_fd);
    cudaGetSymbolAddress((void**)&hmean, g_hmean);
    cudaGetSymbolAddress((void**)&h,     g_h);
    cudaGetSymbolAddress((void**)&bnstat,g_bnstat);
    cudaGetSymbolAddress((void**)&cnt,   g_cnt);
    cudaGetSymbolAddress((void**)&rowptr,g_rowptr);
    cudaGetSymbolAddress((void**)&cursor,g_cursor);
    cudaGetSymbolAddress((void**)&bsum,  g_bsum);
    cudaGetSymbolAddress((void**)&csr,   g_csr);

    const int mt64  = (NN + 63) / 64;               // 782
    const dim3 grid_proj(12, mt64);                 // one matrix each
    const dim3 grid_fc(1, mt64);
    const dim3 grid_out(4, mt64);
    const int nhd_blocks = (NN * HD + 255) / 256;
    const int e3_blocks = (3 * EE + 255) / 256;
    const int seg_blocks = (NSEG + 1023) / 1024;    // 147
    const int gat_blocks = (NN * 32 + 255) / 256;   // warp per dst

    // ---- build dst-CSR once (shared by both layers) ----
    filli_kernel<<<256, 256>>>(cnt, NSEG, 0);
    hist_kernel<<<e3_blocks, 256>>>(dst0, dst1, dst2, cnt);
    scan_block<<<seg_blocks, 1024>>>(cnt, rowptr, bsum, NSEG);
    scan_bsum<<<1, 256>>>(bsum, seg_blocks);
    add_off<<<seg_blocks, 1024>>>(rowptr, cursor, bsum, NSEG);
    scatter_kernel<<<e3_blocks, 256>>>(src0, dst0, src1, dst1, src2, dst2, cursor, csr);

    const float* hin = x;
    for (int l = 0; l < 2; l++) {
        const float* Ws = Wsrc + (size_t)l * 3 * 64 * 256;
        const float* Wd = Wdst + (size_t)l * 3 * 64 * 256;
        gemm_proj<0><<<grid_proj, 128>>>(hin, Ws, fs, NN);   // values: bf16x3
        gemm_proj<1><<<grid_proj, 128>>>(hin, Wd, fd, NN);   // logits: fp16
        gat_fused<<<gat_blocks, 256>>>(fs, fd, rowptr, cursor, csr, hmean);
        gemm_bf16x3<1, 1><<<grid_fc, 128>>>(hmean, Wfc + (size_t)l * 64 * 64,
                                            bfc + l * 64, h, NN, HD, 64);
        fill_kernel<<<1, 128>>>(bnstat, 2 * HD, 0.0f);
        bn_stats_kernel<<<512, 256>>>(h, bnstat);
        bn_norm_kernel<<<nhd_blocks, 256>>>(h, bnstat, gamma + l * 64, beta + l * 64);
        hin = h;
    }
    gemm_bf16x3<1, 0><<<grid_out, 128>>>(h, Wdim, bdim, out, NN, IND, 256);
    (void)in_sizes; (void)n_in; (void)out_size;
}

// round 17
// speedup vs baseline: 1.9926x; 1.0783x over previous
#include <cuda_runtime.h>
#include <cuda_bf16.h>
#include <cuda_fp16.h>
#include <math.h>

#define NN 50000
#define EE 250000
#define HD 64
#define NH 4
#define FDR 768         // 3 relations * 4 heads * 64
#define IND 256
#define SCALEF 0.125f   // 1/sqrt(64)
#define EPS_BN 1e-5f
#define PLD 36          // plane row stride (words), conflict-free (4*gid+tig)
#define NSEG (3 * NN)   // CSR segments

// ---------------- scratch (static device globals; no allocation) -------------
__device__ __half g_fs[(size_t)NN * FDR];
__device__ __half g_fd[(size_t)NN * FDR];
__device__ float g_hmean[NN * HD];
__device__ float g_h[NN * HD];
__device__ float g_bnstat[2 * HD];
__device__ int   g_cnt[NSEG];
__device__ int   g_rowptr[NSEG];
__device__ int   g_cursor[NSEG];
__device__ int   g_bsum[256];
__device__ int   g_csr[3 * EE];

// ---------------- fills -------------------------------------------------------
__global__ void fill_kernel(float* __restrict__ p, int n, float v) {
    int i = blockIdx.x * blockDim.x + threadIdx.x;
    int stride = gridDim.x * blockDim.x;
    for (; i < n; i += stride) p[i] = v;
}
__global__ void filli_kernel(int* __restrict__ p, int n, int v) {
    int i = blockIdx.x * blockDim.x + threadIdx.x;
    int stride = gridDim.x * blockDim.x;
    for (; i < n; i += stride) p[i] = v;
}

// ---------------- CSR build ---------------------------------------------------
__global__ void hist_kernel(const int* __restrict__ d0, const int* __restrict__ d1,
                            const int* __restrict__ d2, int* __restrict__ cnt) {
    int i = blockIdx.x * blockDim.x + threadIdx.x;
    if (i >= 3 * EE) return;
    int r = i / EE, e = i - r * EE;
    const int* dp = (r == 0) ? d0 : (r == 1) ? d1 : d2;
    atomicAdd(&cnt[r * NN + dp[e]], 1);
}

__global__ void scan_block(const int* __restrict__ in, int* __restrict__ out,
                           int* __restrict__ bsum, int n) {
    __shared__ int sh[1024];
    int gid = blockIdx.x * 1024 + threadIdx.x;
    int v = (gid < n) ? in[gid] : 0;
    sh[threadIdx.x] = v;
    __syncthreads();
    for (int off = 1; off < 1024; off <<= 1) {
        int t = (threadIdx.x >= off) ? sh[threadIdx.x - off] : 0;
        __syncthreads();
        sh[threadIdx.x] += t;
        __syncthreads();
    }
    if (gid < n) out[gid] = sh[threadIdx.x] - v;   // exclusive
    if (threadIdx.x == 1023) bsum[blockIdx.x] = sh[1023];
}

__global__ void scan_bsum(int* __restrict__ bsum, int nb) {
    __shared__ int sh[256];
    int v = (threadIdx.x < nb) ? bsum[threadIdx.x] : 0;
    sh[threadIdx.x] = v;
    __syncthreads();
    for (int off = 1; off < 256; off <<= 1) {
        int t = (threadIdx.x >= off) ? sh[threadIdx.x - off] : 0;
        __syncthreads();
        sh[threadIdx.x] += t;
        __syncthreads();
    }
    if (threadIdx.x < nb) bsum[threadIdx.x] = sh[threadIdx.x] - v;  // exclusive
}

__global__ void add_off(int* __restrict__ rowptr, int* __restrict__ cursor,
                        const int* __restrict__ bsum, int n) {
    int gid = blockIdx.x * 1024 + threadIdx.x;
    if (gid < n) {
        int v = rowptr[gid] + bsum[blockIdx.x];
        rowptr[gid] = v;
        cursor[gid] = v;
    }
}

__global__ void scatter_kernel(const int* __restrict__ s0, const int* __restrict__ d0,
                               const int* __restrict__ s1, const int* __restrict__ d1,
                               const int* __restrict__ s2, const int* __restrict__ d2,
                               int* __restrict__ cursor, int* __restrict__ csr) {
    int i = blockIdx.x * blockDim.x + threadIdx.x;
    if (i >= 3 * EE) return;
    int r = i / EE, e = i - r * EE;
    const int* sp = (r == 0) ? s0 : (r == 1) ? s1 : s2;
    const int* dp = (r == 0) ? d0 : (r == 1) ? d1 : d2;
    int pos = atomicAdd(&cursor[r * NN + dp[e]], 1);
    csr[pos] = sp[e];
}

// ---------------- pack helpers ------------------------------------------------
__device__ __forceinline__ unsigned packh2(float a, float b) {
    __half2 h = __floats2half2_rn(a, b);
    return *reinterpret_cast<unsigned*>(&h);
}
// fp16 error-free-ish split: x = h0 + h1 (22 mantissa bits)
__device__ __forceinline__ void hsplit(float x, unsigned short& h0, unsigned short& h1) {
    __half a = __float2half_rn(x);
    h0 = __half_as_ushort(a);
    h1 = __half_as_ushort(__float2half_rn(x - __half2float(a)));
}
__device__ __forceinline__ unsigned pack2(unsigned short lo, unsigned short hi) {
    return (unsigned)lo | ((unsigned)hi << 16);
}
__device__ __forceinline__ void mma_f16(float* c,
                                        unsigned a0, unsigned a1, unsigned a2, unsigned a3,
                                        unsigned b0, unsigned b1) {
    asm volatile("mma.sync.aligned.m16n8k16.row.col.f32.f16.f16.f32 "
                 "{%0,%1,%2,%3}, {%4,%5,%6,%7}, {%8,%9}, {%0,%1,%2,%3};"
                 : "+f"(c[0]), "+f"(c[1]), "+f"(c[2]), "+f"(c[3])
                 : "r"(a0), "r"(a1), "r"(a2), "r"(a3), "r"(b0), "r"(b1));
}

// ---------------- unified GEMM: C[M,NcC] = A[M,64] @ B-blocks ----------------
// 64x64 block tile, 128 threads = 4 warps (2x2), warp tile 32x32.
// NPL=1: plain fp16 (logits).  NPL=2: fp16 A-split, 2 MMAs (value/fc/out paths;
//        only B-quantization error ~2.4e-4).
// OUTH=1: fp16 output (packed half2). OUTH=0: fp32 output (+bias)(+relu).
template <int NPL, int OUTH, int BIAS, int RELU>
__global__ void gemm_f16(const float* __restrict__ A,
                         const float* __restrict__ B,
                         const float* __restrict__ bias,
                         void* __restrict__ C,
                         int M, int NcC, int ldb) {
    __shared__ unsigned Ab[NPL][64][PLD];
    __shared__ unsigned Bb[64][PLD];

    const int bm = blockIdx.y * 64;
    const int bn = blockIdx.x * 64;
    const int tid = threadIdx.x;
    const float* Bblk = B + (size_t)(bn >> 8) * (64 * 256) + (bn & 255);

    // A tile: 64 rows x 16 k-quads
    for (int i = tid; i < 64 * 16; i += 128) {
        int r = i >> 4, q = i & 15;
        int gr = bm + r;
        float4 v = make_float4(0.f, 0.f, 0.f, 0.f);
        if (gr < M) v = *reinterpret_cast<const float4*>(&A[(size_t)gr * 64 + 4 * q]);
        if (NPL == 1) {
            Ab[0][r][2 * q]     = packh2(v.x, v.y);
            Ab[0][r][2 * q + 1] = packh2(v.z, v.w);
        } else {
            unsigned short x0, x1, y0, y1, z0, z1, w0, w1;
            hsplit(v.x, x0, x1); hsplit(v.y, y0, y1);
            hsplit(v.z, z0, z1); hsplit(v.w, w0, w1);
            Ab[0][r][2 * q]     = pack2(x0, y0);
            Ab[0][r][2 * q + 1] = pack2(z0, w0);
            Ab[NPL - 1][r][2 * q]     = pack2(x1, y1);
            Ab[NPL - 1][r][2 * q + 1] = pack2(z1, w1);
        }
    }
    // B tile: 32 k-pairs x 16 n-quads; transpose into [n][kpair], single plane
    for (int i = tid; i < 32 * 16; i += 128) {
        int j = i >> 4, q = i & 15;
        float4 v0 = *reinterpret_cast<const float4*>(&Bblk[(size_t)(2 * j) * ldb + 4 * q]);
        float4 v1 = *reinterpret_cast<const float4*>(&Bblk[(size_t)(2 * j + 1) * ldb + 4 * q]);
        const float e0[4] = {v0.x, v0.y, v0.z, v0.w};
        const float e1[4] = {v1.x, v1.y, v1.z, v1.w};
#pragma unroll
        for (int c = 0; c < 4; c++)
            Bb[4 * q + c][j] = packh2(e0[c], e1[c]);
    }
    __syncthreads();

    const int warp = tid >> 5, lane = tid & 31;
    const int rowg = warp >> 1, colg = warp & 1;
    const int rbase = rowg * 32, cbase = colg * 32;
    const int gid = lane >> 2, tig = lane & 3;

    float acc[2][4][4];
#pragma unroll
    for (int mb = 0; mb < 2; mb++)
#pragma unroll
        for (int nt = 0; nt < 4; nt++)
#pragma unroll
            for (int j = 0; j < 4; j++) acc[mb][nt][j] = 0.0f;

#pragma unroll
    for (int kc = 0; kc < 4; kc++) {
        const int kb = kc * 8;
        unsigned a[NPL][2][4];
#pragma unroll
        for (int p = 0; p < NPL; p++)
#pragma unroll
            for (int mb = 0; mb < 2; mb++) {
                const int r0 = rbase + mb * 16 + gid;
                a[p][mb][0] = Ab[p][r0][kb + tig];
                a[p][mb][1] = Ab[p][r0 + 8][kb + tig];
                a[p][mb][2] = Ab[p][r0][kb + tig + 4];
                a[p][mb][3] = Ab[p][r0 + 8][kb + tig + 4];
            }
#pragma unroll
        for (int nt = 0; nt < 4; nt++) {
            int n = cbase + nt * 8 + gid;
            unsigned b0 = Bb[n][kb + tig];
            unsigned b1 = Bb[n][kb + tig + 4];
#pragma unroll
            for (int mb = 0; mb < 2; mb++)
#pragma unroll
                for (int p = 0; p < NPL; p++)
                    mma_f16(acc[mb][nt], a[p][mb][0], a[p][mb][1],
                            a[p][mb][2], a[p][mb][3], b0, b1);
        }
    }

#pragma unroll
    for (int mb = 0; mb < 2; mb++)
#pragma unroll
        for (int nt = 0; nt < 4; nt++) {
            int c = cbase + nt * 8 + 2 * tig;
            float bb0 = 0.f, bb1 = 0.f;
            if (BIAS) { bb0 = bias[bn + c]; bb1 = bias[bn + c + 1]; }
#pragma unroll
            for (int half = 0; half < 2; half++) {
                int gr = bm + rbase + mb * 16 + gid + half * 8;
                if (gr >= M) continue;
                float v0 = acc[mb][nt][half * 2 + 0] + bb0;
                float v1 = acc[mb][nt][half * 2 + 1] + bb1;
                if (RELU) { v0 = fmaxf(v0, 0.0f); v1 = fmaxf(v1, 0.0f); }
                if (OUTH) {
                    __half* Ch = (__half*)C;
                    *reinterpret_cast<unsigned*>(&Ch[(size_t)gr * NcC + bn + c]) =
                        packh2(v0, v1);
                } else {
                    float* Cf = (float*)C;
                    *reinterpret_cast<float2*>(&Cf[(size_t)gr * NcC + bn + c]) =
                        make_float2(v0, v1);
                }
            }
        }
}

// ---------------- fp16 row load: 8 halves -> 4 float2 ------------------------
__device__ __forceinline__ void ld8h(const __half* p, float2& a, float2& b,
                                     float2& c, float2& d) {
    uint4 rv = *reinterpret_cast<const uint4*>(p);
    a = __half22float2(*reinterpret_cast<__half2*>(&rv.x));
    b = __half22float2(*reinterpret_cast<__half2*>(&rv.y));
    c = __half22float2(*reinterpret_cast<__half2*>(&rv.z));
    d = __half22float2(*reinterpret_cast<__half2*>(&rv.w));
}

// ---------------- fused GAT: softmax + aggregate + head-mean, warp per dst ---
__global__ void gat_fused(const __half* __restrict__ fs,
                          const __half* __restrict__ fd,
                          const int* __restrict__ rowptr,
                          const int* __restrict__ rowend,
                          const int* __restrict__ csr,
                          float* __restrict__ hmean) {
    int w = (blockIdx.x * blockDim.x + threadIdx.x) >> 5;
    if (w >= NN) return;
    int lane = threadIdx.x & 31;
    float out[8];
#pragma unroll
    for (int j = 0; j < 8; j++) out[j] = 0.f;

#pragma unroll
    for (int r = 0; r < 3; r++) {
        float2 d0, d1, d2, d3;
        ld8h(fd + (size_t)w * FDR + r * 256 + 8 * lane, d0, d1, d2, d3);
        float accv[8];
#pragma unroll
        for (int j = 0; j < 8; j++) accv[j] = 0.f;
        float dn = 0.f;
        int idx = r * NN + w;
        int beg = rowptr[idx];
        int end = rowend[idx];
        int i = beg;
        for (; i + 2 <= end; i += 2) {
            int s0 = csr[i], s1 = csr[i + 1];
            float2 a0, a1, a2, a3, b0, b1, b2, b3;
            ld8h(fs + (size_t)s0 * FDR + r * 256 + 8 * lane, a0, a1, a2, a3);
            ld8h(fs + (size_t)s1 * FDR + r * 256 + 8 * lane, b0, b1, b2, b3);
            float dA = a0.x * d0.x + a0.y * d0.y + a1.x * d1.x + a1.y * d1.y +
                       a2.x * d2.x + a2.y * d2.y + a3.x * d3.x + a3.y * d3.y;
            float dB = b0.x * d0.x + b0.y * d0.y + b1.x * d1.x + b1.y * d1.y +
                       b2.x * d2.x + b2.y * d2.y + b3.x * d3.x + b3.y * d3.y;
            dA += __shfl_xor_sync(0xffffffffu, dA, 4);
            dB += __shfl_xor_sync(0xffffffffu, dB, 4);
            dA += __shfl_xor_sync(0xffffffffu, dA, 2);
            dB += __shfl_xor_sync(0xffffffffu, dB, 2);
            dA += __shfl_xor_sync(0xffffffffu, dA, 1);
            dB += __shfl_xor_sync(0xffffffffu, dB, 1);
            float pA = __expf(dA * SCALEF);
            float pB = __expf(dB * SCALEF);
            dn += pA + pB;
            accv[0] += pA * a0.x + pB * b0.x; accv[1] += pA * a0.y + pB * b0.y;
            accv[2] += pA * a1.x + pB * b1.x; accv[3] += pA * a1.y + pB * b1.y;
            accv[4] += pA * a2.x + pB * b2.x; accv[5] += pA * a2.y + pB * b2.y;
            accv[6] += pA * a3.x + pB * b3.x; accv[7] += pA * a3.y + pB * b3.y;
        }
        if (i < end) {
            int s = csr[i];
            float2 f0, f1, f2, f3;
            ld8h(fs + (size_t)s * FDR + r * 256 + 8 * lane, f0, f1, f2, f3);
            float dot = f0.x * d0.x + f0.y * d0.y + f1.x * d1.x + f1.y * d1.y +
                        f2.x * d2.x + f2.y * d2.y + f3.x * d3.x + f3.y * d3.y;
            dot += __shfl_xor_sync(0xffffffffu, dot, 4);
            dot += __shfl_xor_sync(0xffffffffu, dot, 2);
            dot += __shfl_xor_sync(0xffffffffu, dot, 1);
            float p = __expf(dot * SCALEF);
            dn += p;
            accv[0] += p * f0.x; accv[1] += p * f0.y;
            accv[2] += p * f1.x; accv[3] += p * f1.y;
            accv[4] += p * f2.x; accv[5] += p * f2.y;
            accv[6] += p * f3.x; accv[7] += p * f3.y;
        }
        float inv = 0.25f / fmaxf(dn, 1e-9f);
#pragma unroll
        for (int j = 0; j < 8; j++) out[j] += accv[j] * inv;
    }
#pragma unroll
    for (int j = 0; j < 8; j++) {
        out[j] += __shfl_xor_sync(0xffffffffu, out[j], 8);
        out[j] += __shfl_xor_sync(0xffffffffu, out[j], 16);
    }
    if (lane < 8) {
        float4* ph = reinterpret_cast<float4*>(hmean + (size_t)w * HD + 8 * lane);
        ph[0] = make_float4(out[0], out[1], out[2], out[3]);
        ph[1] = make_float4(out[4], out[5], out[6], out[7]);
    }
}

// ---------------- batchnorm --------------------------------------------------
__global__ void bn_stats_kernel(const float* __restrict__ x,
                                float* __restrict__ bnstat) {
    int ch = threadIdx.x & 63;
    int rr = threadIdx.x >> 6;
    float s = 0.0f, s2 = 0.0f;
    for (int n = blockIdx.x * 4 + rr; n < NN; n += gridDim.x * 4) {
        float v = x[n * HD + ch];
        s += v; s2 += v * v;
    }
    __shared__ float sh[256], sh2[256];
    sh[threadIdx.x] = s; sh2[threadIdx.x] = s2;
    __syncthreads();
    if (rr == 0) {
        s  = sh[ch] + sh[64 + ch] + sh[128 + ch] + sh[192 + ch];
        s2 = sh2[ch] + sh2[64 + ch] + sh2[128 + ch] + sh2[192 + ch];
        atomicAdd(&bnstat[ch], s);
        atomicAdd(&bnstat[64 + ch], s2);
    }
}

__global__ void bn_norm_kernel(float* __restrict__ x,
                               const float* __restrict__ bnstat,
                               const float* __restrict__ gamma,
                               const float* __restrict__ beta) {
    int idx = blockIdx.x * blockDim.x + threadIdx.x;
    if (idx >= NN * HD) return;
    int ch = idx & 63;
    float mu = bnstat[ch] * (1.0f / NN);
    float var = bnstat[64 + ch] * (1.0f / NN) - mu * mu;
    float inv = rsqrtf(var + EPS_BN);
    x[idx] = gamma[ch] * (x[idx] - mu) * inv + beta[ch];
}

// ---------------- host orchestration -----------------------------------------
extern "C" void kernel_launch(void* const* d_in, const int* in_sizes, int n_in,
                              void* d_out, int out_size) {
    const float* x    = (const float*)d_in[0];
    const int* src0 = (const int*)d_in[1];
    const int* dst0 = (const int*)d_in[2];
    const int* src1 = (const int*)d_in[3];
    const int* dst1 = (const int*)d_in[4];
    const int* src2 = (const int*)d_in[5];
    const int* dst2 = (const int*)d_in[6];
    const float* Wsrc = (const float*)d_in[7];
    const float* Wdst = (const float*)d_in[8];
    const float* Wfc  = (const float*)d_in[9];
    const float* bfc  = (const float*)d_in[10];
    const float* gamma= (const float*)d_in[11];
    const float* beta = (const float*)d_in[12];
    const float* Wdim = (const float*)d_in[13];
    const float* bdim = (const float*)d_in[14];
    float* out = (float*)d_out;

    __half *fs, *fd;
    float *hmean, *h, *bnstat;
    int *cnt, *rowptr, *cursor, *bsum, *csr;
    cudaGetSymbolAddress((void**)&fs,    g_fs);
    cudaGetSymbolAddress((void**)&fd,    g_fd);
    cudaGetSymbolAddress((void**)&hmean, g_hmean);
    cudaGetSymbolAddress((void**)&h,     g_h);
    cudaGetSymbolAddress((void**)&bnstat,g_bnstat);
    cudaGetSymbolAddress((void**)&cnt,   g_cnt);
    cudaGetSymbolAddress((void**)&rowptr,g_rowptr);
    cudaGetSymbolAddress((void**)&cursor,g_cursor);
    cudaGetSymbolAddress((void**)&bsum,  g_bsum);
    cudaGetSymbolAddress((void**)&csr,   g_csr);

    const int mt64  = (NN + 63) / 64;               // 782
    const dim3 grid_proj(12, mt64);
    const dim3 grid_fc(1, mt64);
    const dim3 grid_out(4, mt64);
    const int nhd_blocks = (NN * HD + 255) / 256;
    const int e3_blocks = (3 * EE + 255) / 256;
    const int seg_blocks = (NSEG + 1023) / 1024;    // 147
    const int gat_blocks = (NN * 32 + 255) / 256;   // warp per dst

    // ---- CSR prefix (launches 1-5), then layer-0 projections (6-7) so the
    //      ncu capture slot lands on the hot fs-proj GEMM, then scatter (8).
    filli_kernel<<<256, 256>>>(cnt, NSEG, 0);
    hist_kernel<<<e3_blocks, 256>>>(dst0, dst1, dst2, cnt);
    scan_block<<<seg_blocks, 1024>>>(cnt, rowptr, bsum, NSEG);
    scan_bsum<<<1, 256>>>(bsum, seg_blocks);
    add_off<<<seg_blocks, 1024>>>(rowptr, cursor, bsum, NSEG);

    gemm_f16<2, 1, 0, 0><<<grid_proj, 128>>>(x, Wsrc, nullptr, fs, NN, FDR, 256);
    gemm_f16<1, 1, 0, 0><<<grid_proj, 128>>>(x, Wdst, nullptr, fd, NN, FDR, 256);

    scatter_kernel<<<e3_blocks, 256>>>(src0, dst0, src1, dst1, src2, dst2, cursor, csr);

    const float* hin = x;
    for (int l = 0; l < 2; l++) {
        if (l > 0) {
            const float* Ws = Wsrc + (size_t)l * 3 * 64 * 256;
            const float* Wd = Wdst + (size_t)l * 3 * 64 * 256;
            gemm_f16<2, 1, 0, 0><<<grid_proj, 128>>>(hin, Ws, nullptr, fs, NN, FDR, 256);
            gemm_f16<1, 1, 0, 0><<<grid_proj, 128>>>(hin, Wd, nullptr, fd, NN, FDR, 256);
        }
        gat_fused<<<gat_blocks, 256>>>(fs, fd, rowptr, cursor, csr, hmean);
        gemm_f16<2, 0, 1, 1><<<grid_fc, 128>>>(hmean, Wfc + (size_t)l * 64 * 64,
                                               bfc + l * 64, h, NN, HD, 64);
        fill_kernel<<<1, 128>>>(bnstat, 2 * HD, 0.0f);
        bn_stats_kernel<<<512, 256>>>(h, bnstat);
        bn_norm_kernel<<<nhd_blocks, 256>>>(h, bnstat, gamma + l * 64, beta + l * 64);
        hin = h;
    }
    gemm_f16<2, 0, 1, 0><<<grid_out, 128>>>(h, Wdim, bdim, out, NN, IND, 256);
    (void)in_sizes; (void)n_in; (void)out_size;
}